// round 9
// baseline (speedup 1.0000x reference)
#include <cuda_runtime.h>
#include <cuda_fp16.h>
#include <math.h>

#define NN 100000
#define EE 3200000
#define NBLK 98   // ceil(NN/1024)

// ---------------- scratch (device globals; no runtime allocation) ----------------
// zeroed each run by one cudaMemsetAsync (memset node in the graph)
struct ZBlock {
    unsigned long long pk[NN];  // {count:24bits | fixed-point weight sum:40bits}
    unsigned int agg[NBLK];     // decoupled-lookback aggregates (bit31 = ready)
};
__device__ ZBlock gz;

__device__ float g_dis[NN];
__device__ int   g_cnt[NN];
__device__ int   g_off[NN];
__device__ int   g_sidx[EE];                  // per-edge slot within its dst bucket
__device__ unsigned long long g_edge[EE];     // packed {norm:f32 (hi), src:i32 (lo)}
__device__ __align__(8) float2 g_axx[NN];     // (Ax[n], x[n])
__device__ __align__(16) uint2 g_fa[NN*16];   // conv1 fp16 feats ping (12 of 16 chunks; 128B/node)
__device__ __align__(16) uint2 g_fb[NN*16];   // conv1 fp16 feats pong
__device__ float g_ca[NN];                    // conv2 Horner scalar, ping
__device__ float g_cb[NN];                    // conv2 Horner scalar, pong
__device__ __align__(16) float4 g_s[NN];      // (s3, s2, s1, s0) per node

// ---------------- gcn_norm + CSR build ----------------
// ONE packed 64-bit atomic per edge; the returned old count IS this edge's
// slot index within its destination bucket -> scatter needs no atomic.
__global__ void k_deg(const int* __restrict__ col, const float* __restrict__ ew) {
    int e = blockIdx.x*blockDim.x + threadIdx.x;
    if (e < EE) {
        unsigned long long inc = (1ull << 40) |
            (unsigned long long)(ew[e] * 268435456.f + 0.5f);
        unsigned long long old = atomicAdd(&gz.pk[col[e]], inc);
        g_sidx[e] = (int)(old >> 40);
    }
}

// fused: unpack deg/cnt + dis + block scan + decoupled lookback + offsets
__global__ void __launch_bounds__(1024) k_scan() {
    __shared__ int s[1024];
    __shared__ int sprefix;
    int tid = threadIdx.x, bid = blockIdx.x;
    int i = bid*1024 + tid;
    int v = 0;
    if (i < NN) {
        unsigned long long p = gz.pk[i];
        v = (int)(p >> 40);
        float d = (float)(p & 0xFFFFFFFFFFull) * 3.7252902984619141e-09f; // 2^-28
        g_dis[i] = d > 0.f ? rsqrtf(fmaxf(d, 1e-12f)) : 0.f;
        g_cnt[i] = v;
    }
    s[tid] = v;
    __syncthreads();
    for (int off = 1; off < 1024; off <<= 1) {
        int t = (tid >= off) ? s[tid - off] : 0;
        __syncthreads();
        s[tid] += t;
        __syncthreads();
    }
    int incl = s[tid];
    if (tid == 0) {
        unsigned int aggregate = (unsigned int)s[1023];
        atomicExch(&gz.agg[bid], aggregate | 0x80000000u);
    }
    if (tid < 32) {
        unsigned int sum = 0;
        for (int b = tid; b < bid; b += 32) {
            unsigned int a;
            do { a = *(volatile unsigned int*)&gz.agg[b]; } while (!(a & 0x80000000u));
            sum += a & 0x7fffffffu;
        }
        #pragma unroll
        for (int off = 16; off; off >>= 1) sum += __shfl_xor_sync(0xffffffffu, sum, off);
        if (tid == 0) sprefix = (int)sum;
    }
    __syncthreads();
    if (i < NN) g_off[i] = sprefix + incl - v;   // exclusive global offset
}

// atomic-free scatter using precomputed slot indices
__global__ void k_scatter(const int* __restrict__ row, const int* __restrict__ colv,
                          const float* __restrict__ ew) {
    int e = blockIdx.x*blockDim.x + threadIdx.x;
    if (e < EE) {
        int r = row[e], c = colv[e];
        float nm = g_dis[r] * ew[e] * g_dis[c];
        int p = g_off[c] + g_sidx[e];
        unsigned long long pk =
            (((unsigned long long)(unsigned int)__float_as_int(nm)) << 32) | (unsigned int)r;
        g_edge[p] = pk;
    }
}

// ---------------- conv1 ----------------
// feat layout per node: 16 uint2 chunks (12 used, 128B record, 128B-aligned);
// chunk ch = cidx*3 + k holds fp16 features [4*cidx .. 4*cidx+3] of stack k.
__device__ __forceinline__ uint2 pack4h(float a, float b, float c, float d) {
    __half2 lo = __floats2half2_rn(a, b);
    __half2 hi = __floats2half2_rn(c, d);
    uint2 o;
    o.x = *(unsigned int*)&lo;
    o.y = *(unsigned int*)&hi;
    return o;
}

// Warp per node: lanes stride over edges, shuffle-reduce Ax; lane 0 stores (Ax, x).
__global__ void __launch_bounds__(256)
k_ax(const float* __restrict__ x) {
    int n = (blockIdx.x*256 + threadIdx.x) >> 5;   // grid exact: 12500*8 = 100000
    int lane = threadIdx.x & 31;
    int st = g_off[n], cn = g_cnt[n];
    float s = 0.f;
    for (int j = st + lane; j < st + cn; j += 32) {
        unsigned long long pk = g_edge[j];
        s += __int_as_float((int)(pk >> 32)) * __ldg(&x[(int)(pk & 0xffffffffu)]);
    }
    #pragma unroll
    for (int off = 16; off; off >>= 1) s += __shfl_xor_sync(0xffffffffu, s, off);
    if (lane == 0) {
        float2 o; o.x = s; o.y = __ldg(&x[n]);
        g_axx[n] = o;
    }
}

// conv1 iteration 1 with ON-THE-FLY feature recompute:
// feat0(src) = relu(Ax[src]*iw + x[src]*rw + b) is a rank-2 function of the
// 8-byte (Ax,x) pair, so the gather is a broadcast float2 (1 sector) instead
// of 96B of materialized features. Same warp/half/lane structure as k_iter1;
// epilogue (fused W matmul + root + relu) identical; writes fp16 feats to g_fb.
__global__ void __launch_bounds__(256)
k_first(const float* __restrict__ iw, const float* __restrict__ w,
        const float* __restrict__ rw, const float* __restrict__ bs) {
    __shared__ float wsh[768];
    __shared__ float rwsh[48], bsh[48];
    __shared__ float ex[8][56];
    for (int i = threadIdx.x; i < 768; i += 256) wsh[i] = w[i];
    if (threadIdx.x < 48) { rwsh[threadIdx.x] = rw[threadIdx.x]; bsh[threadIdx.x] = bs[threadIdx.x]; }
    __syncthreads();

    int warp = threadIdx.x >> 5;
    int lane = threadIdx.x & 31;
    int h = lane >> 4, c = lane & 15;
    bool act = c < 12;
    int kk = c % 3, cidx = c / 3;
    int wb = kk*16 + cidx*4;            // in [0,48) even for c>=12 (values unused)
    float iw0 = __ldg(&iw[wb+0]), iw1 = __ldg(&iw[wb+1]);
    float iw2v = __ldg(&iw[wb+2]), iw3 = __ldg(&iw[wb+3]);
    float rw0 = rwsh[wb+0], rw1 = rwsh[wb+1], rw2v = rwsh[wb+2], rw3 = rwsh[wb+3];
    float b0 = bsh[wb+0], b1 = bsh[wb+1], b2v = bsh[wb+2], b3 = bsh[wb+3];

    int n = blockIdx.x*8 + warp;        // grid exact
    int st = g_off[n], cn = g_cnt[n];
    int e_end = st + cn;

    float4 acc = make_float4(0.f, 0.f, 0.f, 0.f);
    int j = st + h;
    while (j + 6 < e_end) {
        unsigned long long p0 = g_edge[j];
        unsigned long long p1 = g_edge[j+2];
        unsigned long long p2 = g_edge[j+4];
        unsigned long long p3 = g_edge[j+6];
        float m0 = __int_as_float((int)(p0 >> 32));
        float m1 = __int_as_float((int)(p1 >> 32));
        float m2 = __int_as_float((int)(p2 >> 32));
        float m3 = __int_as_float((int)(p3 >> 32));
        float2 q0 = __ldg(&g_axx[(int)(p0 & 0xffffffffu)]);
        float2 q1 = __ldg(&g_axx[(int)(p1 & 0xffffffffu)]);
        float2 q2 = __ldg(&g_axx[(int)(p2 & 0xffffffffu)]);
        float2 q3 = __ldg(&g_axx[(int)(p3 & 0xffffffffu)]);
        acc.x += m0*fmaxf(q0.x*iw0 + q0.y*rw0 + b0, 0.f)
               + m1*fmaxf(q1.x*iw0 + q1.y*rw0 + b0, 0.f)
               + m2*fmaxf(q2.x*iw0 + q2.y*rw0 + b0, 0.f)
               + m3*fmaxf(q3.x*iw0 + q3.y*rw0 + b0, 0.f);
        acc.y += m0*fmaxf(q0.x*iw1 + q0.y*rw1 + b1, 0.f)
               + m1*fmaxf(q1.x*iw1 + q1.y*rw1 + b1, 0.f)
               + m2*fmaxf(q2.x*iw1 + q2.y*rw1 + b1, 0.f)
               + m3*fmaxf(q3.x*iw1 + q3.y*rw1 + b1, 0.f);
        acc.z += m0*fmaxf(q0.x*iw2v + q0.y*rw2v + b2v, 0.f)
               + m1*fmaxf(q1.x*iw2v + q1.y*rw2v + b2v, 0.f)
               + m2*fmaxf(q2.x*iw2v + q2.y*rw2v + b2v, 0.f)
               + m3*fmaxf(q3.x*iw2v + q3.y*rw2v + b2v, 0.f);
        acc.w += m0*fmaxf(q0.x*iw3 + q0.y*rw3 + b3, 0.f)
               + m1*fmaxf(q1.x*iw3 + q1.y*rw3 + b3, 0.f)
               + m2*fmaxf(q2.x*iw3 + q2.y*rw3 + b3, 0.f)
               + m3*fmaxf(q3.x*iw3 + q3.y*rw3 + b3, 0.f);
        j += 8;
    }
    while (j < e_end) {
        unsigned long long p0 = g_edge[j];
        float m0 = __int_as_float((int)(p0 >> 32));
        float2 q0 = __ldg(&g_axx[(int)(p0 & 0xffffffffu)]);
        acc.x += m0*fmaxf(q0.x*iw0 + q0.y*rw0 + b0, 0.f);
        acc.y += m0*fmaxf(q0.x*iw1 + q0.y*rw1 + b1, 0.f);
        acc.z += m0*fmaxf(q0.x*iw2v + q0.y*rw2v + b2v, 0.f);
        acc.w += m0*fmaxf(q0.x*iw3 + q0.y*rw3 + b3, 0.f);
        j += 2;
    }

    // combine the two halves
    acc.x += __shfl_xor_sync(0xffffffffu, acc.x, 16);
    acc.y += __shfl_xor_sync(0xffffffffu, acc.y, 16);
    acc.z += __shfl_xor_sync(0xffffffffu, acc.z, 16);
    acc.w += __shfl_xor_sync(0xffffffffu, acc.w, 16);

    bool act0 = (h == 0) && act;
    if (act0) {
        float* e = ex[warp] + wb;
        e[0] = acc.x; e[1] = acc.y; e[2] = acc.z; e[3] = acc.w;
    }
    __syncwarp();

    // y = af * W[k] + x*root_w + bias, relu  (A(out)w == A(out w))
    if (act0) {
        const float* af = ex[warp] + kk*16;
        const float* wk = wsh + kk*256;
        float xv = g_axx[n].y;
        float py[4];
        #pragma unroll
        for (int i = 0; i < 4; i++) {
            int oo = cidx*4 + i;
            float y = 0.f;
            #pragma unroll
            for (int f = 0; f < 16; f++) y += af[f] * wk[f*16 + oo];
            py[i] = fmaxf(y + xv*rwsh[kk*16+oo] + bsh[kk*16+oo], 0.f);
        }
        g_fb[n*16 + c] = pack4h(py[0], py[1], py[2], py[3]);
    }
}

// Warp per node, dual-edge halves, unroll-4 pipelined fp16 gather (iters 2,3).
// finalMode fuses mean/BN/relu + conv2 Horner prep.
__global__ void __launch_bounds__(256)
k_iter1(int srcIsB, int finalMode,
        const float* __restrict__ x, const float* __restrict__ w,
        const float* __restrict__ rw, const float* __restrict__ bs,
        const float* __restrict__ bng, const float* __restrict__ bnb,
        const float* __restrict__ bnm, const float* __restrict__ bnv,
        const float* __restrict__ iw2, const float* __restrict__ w2,
        const float* __restrict__ rw2, const float* __restrict__ b2) {
    __shared__ float wsh[768];
    __shared__ float rwsh[48], bsh[48];
    __shared__ float ex[8][56];
    for (int i = threadIdx.x; i < 768; i += 256) wsh[i] = w[i];
    if (threadIdx.x < 48) { rwsh[threadIdx.x] = rw[threadIdx.x]; bsh[threadIdx.x] = bs[threadIdx.x]; }
    __syncthreads();

    int warp = threadIdx.x >> 5;
    int lane = threadIdx.x & 31;
    int h = lane >> 4, c = lane & 15;
    bool act = c < 12;
    int n = blockIdx.x*8 + warp;                 // grid exact
    int st = g_off[n], cn = g_cnt[n];
    int e_end = st + cn;
    const uint2* F = srcIsB ? g_fb : g_fa;
    uint2*       D = srcIsB ? g_fa : g_fb;

    float4 acc = make_float4(0.f, 0.f, 0.f, 0.f);
    int j = st + h;
    while (j + 6 < e_end) {
        unsigned long long p0 = g_edge[j];
        unsigned long long p1 = g_edge[j+2];
        unsigned long long p2 = g_edge[j+4];
        unsigned long long p3 = g_edge[j+6];
        float m0 = __int_as_float((int)(p0 >> 32));
        float m1 = __int_as_float((int)(p1 >> 32));
        float m2 = __int_as_float((int)(p2 >> 32));
        float m3 = __int_as_float((int)(p3 >> 32));
        int s0 = (int)(p0 & 0xffffffffu);
        int s1 = (int)(p1 & 0xffffffffu);
        int s2 = (int)(p2 & 0xffffffffu);
        int s3 = (int)(p3 & 0xffffffffu);
        if (act) {
            uint2 q0 = __ldg(&F[s0*16 + c]);
            uint2 q1 = __ldg(&F[s1*16 + c]);
            uint2 q2 = __ldg(&F[s2*16 + c]);
            uint2 q3 = __ldg(&F[s3*16 + c]);
            float2 a0 = __half22float2(*(const __half2*)&q0.x);
            float2 b0 = __half22float2(*(const __half2*)&q0.y);
            float2 a1 = __half22float2(*(const __half2*)&q1.x);
            float2 b1 = __half22float2(*(const __half2*)&q1.y);
            float2 a2 = __half22float2(*(const __half2*)&q2.x);
            float2 b2v = __half22float2(*(const __half2*)&q2.y);
            float2 a3 = __half22float2(*(const __half2*)&q3.x);
            float2 b3 = __half22float2(*(const __half2*)&q3.y);
            acc.x += m0*a0.x + m1*a1.x + m2*a2.x + m3*a3.x;
            acc.y += m0*a0.y + m1*a1.y + m2*a2.y + m3*a3.y;
            acc.z += m0*b0.x + m1*b1.x + m2*b2v.x + m3*b3.x;
            acc.w += m0*b0.y + m1*b1.y + m2*b2v.y + m3*b3.y;
        }
        j += 8;
    }
    while (j < e_end) {
        unsigned long long p0 = g_edge[j];
        float m0 = __int_as_float((int)(p0 >> 32));
        int s0 = (int)(p0 & 0xffffffffu);
        if (act) {
            uint2 q0 = __ldg(&F[s0*16 + c]);
            float2 a0 = __half22float2(*(const __half2*)&q0.x);
            float2 b0 = __half22float2(*(const __half2*)&q0.y);
            acc.x += m0*a0.x; acc.y += m0*a0.y; acc.z += m0*b0.x; acc.w += m0*b0.y;
        }
        j += 2;
    }

    // combine the two halves
    acc.x += __shfl_xor_sync(0xffffffffu, acc.x, 16);
    acc.y += __shfl_xor_sync(0xffffffffu, acc.y, 16);
    acc.z += __shfl_xor_sync(0xffffffffu, acc.z, 16);
    acc.w += __shfl_xor_sync(0xffffffffu, acc.w, 16);

    int kk = c % 3, cidx = c / 3;   // chunk c = cidx*3 + kk
    bool act0 = (h == 0) && act;
    if (act0) {
        float* e = ex[warp] + kk*16 + cidx*4;
        e[0] = acc.x; e[1] = acc.y; e[2] = acc.z; e[3] = acc.w;
    }
    __syncwarp();

    // y = af * W[k] + x*root_w + bias, relu  (A(out)w == A(out w))
    float4 yv = make_float4(0.f, 0.f, 0.f, 0.f);
    if (act0) {
        const float* af = ex[warp] + kk*16;
        const float* wk = wsh + kk*256;
        float xv = __ldg(&x[n]);
        float* py = (float*)&yv;
        #pragma unroll
        for (int i = 0; i < 4; i++) {
            int oo = cidx*4 + i;
            float y = 0.f;
            #pragma unroll
            for (int f = 0; f < 16; f++) y += af[f] * wk[f*16 + oo];
            py[i] = fmaxf(y + xv*rwsh[kk*16+oo] + bsh[kk*16+oo], 0.f);
        }
    }
    __syncwarp();

    if (!finalMode) {
        if (act0) D[n*16 + c] = pack4h(yv.x, yv.y, yv.z, yv.w);
        return;
    }

    // ---- final iteration: mean over stacks + BN + relu + conv2 Horner prep ----
    if (act0) {
        float* e = ex[warp] + kk*16 + cidx*4;
        e[0] = yv.x; e[1] = yv.y; e[2] = yv.z; e[3] = yv.w;
    }
    __syncwarp();
    if (lane < 16) {
        float m = (ex[warp][lane] + ex[warp][16+lane] + ex[warp][32+lane]) * (1.f/3.f);
        float sc = __ldg(&bng[lane]) * rsqrtf(__ldg(&bnv[lane]) + 1e-5f);
        ex[warp][lane] = fmaxf((m - __ldg(&bnm[lane]))*sc + __ldg(&bnb[lane]), 0.f);
    }
    __syncwarp();
    if (lane == 0) {
        float hv[16];
        #pragma unroll
        for (int f = 0; f < 16; f++) hv[f] = ex[warp][f];
        float o[3] = {0,0,0}, r[3] = {0,0,0};
        #pragma unroll
        for (int k2 = 0; k2 < 3; k2++) {
            #pragma unroll
            for (int f = 0; f < 16; f++) {
                o[k2] += hv[f] * __ldg(&iw2[k2*16+f]);
                r[k2] += hv[f] * __ldg(&rw2[k2*16+f]);
            }
            r[k2] += __ldg(&b2[k2]);
        }
        float z = 0.f, s3v = 0.f, s2v = 0.f, s1v = 0.f, s0v = 0.f;
        #pragma unroll
        for (int k2 = 0; k2 < 3; k2++) {
            float wv = __ldg(&w2[k2]);
            float w2p = wv*wv, w3p = w2p*wv;
            z   += w3p * o[k2];
            s3v += w3p * r[k2];
            s2v += w2p * r[k2];
            s1v += wv  * r[k2];
            s0v += r[k2];
        }
        g_ca[n] = z;
        float4 sv; sv.x = s3v; sv.y = s2v; sv.z = s1v; sv.w = s0v;
        g_s[n] = sv;
    }
}

// ---------------- conv2: 4 scalar Horner SpMV passes ----------------
// result = sigmoid( (A(A(A(A z + s3) + s2) + s1) + s0) / 3 )
// Half-warp per node: 2 nodes/warp, 4-level shuffle reduce.
__global__ void __launch_bounds__(256)
k_sp(int pass, float* __restrict__ finalOut) {
    int n = (blockIdx.x*256 + threadIdx.x) >> 4;   // grid exact: 6250*16 = 100000
    int lane = threadIdx.x & 15;
    int st = g_off[n], cn = g_cnt[n];
    const float* src = (pass & 1) ? g_cb : g_ca;
    float s = 0.f;
    for (int j = st + lane; j < st + cn; j += 16) {
        unsigned long long pk = g_edge[j];
        s += __int_as_float((int)(pk >> 32)) * __ldg(&src[(int)(pk & 0xffffffffu)]);
    }
    #pragma unroll
    for (int off = 8; off; off >>= 1) s += __shfl_xor_sync(0xffffffffu, s, off);
    if (lane == 0) {
        float4 sv = __ldg(&g_s[n]);
        float si = (pass == 0) ? sv.x : (pass == 1) ? sv.y : (pass == 2) ? sv.z : sv.w;
        float cval = s + si;
        if (pass == 3) {
            finalOut[n] = 1.f / (1.f + expf(-cval * (1.f/3.f)));
        } else {
            float* dst = (pass & 1) ? g_ca : g_cb;
            dst[n] = cval;
        }
    }
}

// ---------------- driver ----------------
extern "C" void kernel_launch(void* const* d_in, const int* in_sizes, int n_in,
                              void* d_out, int out_size) {
    const float* x    = (const float*)d_in[0];
    const int*   ei   = (const int*)  d_in[1];
    const float* ew   = (const float*)d_in[2];
    const float* c1iw = (const float*)d_in[3];
    const float* c1w  = (const float*)d_in[4];
    const float* c1rw = (const float*)d_in[5];
    const float* c1b  = (const float*)d_in[6];
    const float* bng  = (const float*)d_in[7];
    const float* bnb  = (const float*)d_in[8];
    const float* bnm  = (const float*)d_in[9];
    const float* bnv  = (const float*)d_in[10];
    const float* c2iw = (const float*)d_in[11];
    const float* c2w  = (const float*)d_in[12];
    const float* c2rw = (const float*)d_in[13];
    const float* c2b  = (const float*)d_in[14];
    float* out = (float*)d_out;

    const int* row = ei;
    const int* col = ei + EE;

    const int EG = (EE + 255) / 256;
    const int WG = 12500;   // warp-per-node: 12500 blocks x 8 warps = 100000
    const int HG = 6250;    // half-warp-per-node: 6250 blocks x 16 halves = 100000

    // zero packed deg/cnt + lookback aggregates in one memset node
    void* zp = nullptr;
    cudaGetSymbolAddress(&zp, gz);
    cudaMemsetAsync(zp, 0, sizeof(ZBlock), 0);

    // gcn_norm + CSR build (scatter is atomic-free via slot indices from k_deg)
    k_deg<<<EG, 256>>>(col, ew);
    k_scan<<<NBLK, 1024>>>();
    k_scatter<<<EG, 256>>>(row, col, ew);

    // conv1: rank-1 first propagation, on-the-fly pass 1, then 2 fp16 SpMM iters
    k_ax<<<WG, 256>>>(x);
    k_first<<<WG, 256>>>(c1iw, c1w, c1rw, c1b);                                              // (Ax,x) -> fb
    k_iter1<<<WG, 256>>>(1, 0, x, c1w, c1rw, c1b, bng, bnb, bnm, bnv, c2iw, c2w, c2rw, c2b); // fb -> fa
    k_iter1<<<WG, 256>>>(0, 1, x, c1w, c1rw, c1b, bng, bnb, bnm, bnv, c2iw, c2w, c2rw, c2b); // fa -> Horner prep

    // conv2: 4 scalar Horner passes, last fuses sigmoid -> out
    k_sp<<<HG, 256>>>(0, nullptr);  // ca -> cb  (+s3)
    k_sp<<<HG, 256>>>(1, nullptr);  // cb -> ca  (+s2)
    k_sp<<<HG, 256>>>(2, nullptr);  // ca -> cb  (+s1)
    k_sp<<<HG, 256>>>(3, out);      // cb -> sigmoid((c+s0)/3) -> out
}

// round 10
// speedup vs baseline: 1.0372x; 1.0372x over previous
#include <cuda_runtime.h>
#include <cuda_fp16.h>
#include <math.h>

#define NN 100000
#define EE 3200000
#define NBLK 98   // ceil(NN/1024)

// ---------------- scratch (device globals; no runtime allocation) ----------------
// zeroed each run by one cudaMemsetAsync (memset node in the graph)
struct ZBlock {
    unsigned long long pk[NN];  // {count:24bits | fixed-point weight sum:40bits}
    float        ax[NN];        // Ax accumulator (REDG from k_scatter)
    unsigned int agg[NBLK];     // decoupled-lookback aggregates (bit31 = ready)
};
__device__ ZBlock gz;

__device__ float g_dis[NN];
__device__ int   g_cnt[NN];
__device__ int   g_off[NN];
__device__ int   g_cur[NN];
__device__ unsigned long long g_edge[EE];     // packed {norm:f32 (hi), src:i32 (lo)}
__device__ __align__(16) uint2 g_fa[NN*16];   // conv1 fp16 feats ping (12 of 16 chunks; 128B/node)
__device__ __align__(16) uint2 g_fb[NN*16];   // conv1 fp16 feats pong
__device__ float g_ca[NN];                    // conv2 Horner scalar, ping
__device__ float g_cb[NN];                    // conv2 Horner scalar, pong
__device__ __align__(16) float4 g_s[NN];      // (s3, s2, s1, s0) per node

// ---------------- gcn_norm + CSR build ----------------
// ONE packed 64-bit fire-and-forget atomic per edge (REDG): high 24 bits
// count, low 40 bits fixed-point (2^-28) sum of edge weights.
__global__ void k_deg(const int* __restrict__ col, const float* __restrict__ ew) {
    int e = blockIdx.x*blockDim.x + threadIdx.x;
    if (e < EE) {
        unsigned long long inc = (1ull << 40) |
            (unsigned long long)(ew[e] * 268435456.f + 0.5f);
        atomicAdd(&gz.pk[col[e]], inc);
    }
}

// fused: unpack deg/cnt + dis + block scan + decoupled lookback + offsets
__global__ void __launch_bounds__(1024) k_scan() {
    __shared__ int s[1024];
    __shared__ int sprefix;
    int tid = threadIdx.x, bid = blockIdx.x;
    int i = bid*1024 + tid;
    int v = 0;
    if (i < NN) {
        unsigned long long p = gz.pk[i];
        v = (int)(p >> 40);
        float d = (float)(p & 0xFFFFFFFFFFull) * 3.7252902984619141e-09f; // 2^-28
        g_dis[i] = d > 0.f ? rsqrtf(fmaxf(d, 1e-12f)) : 0.f;
        g_cnt[i] = v;
    }
    s[tid] = v;
    __syncthreads();
    for (int off = 1; off < 1024; off <<= 1) {
        int t = (tid >= off) ? s[tid - off] : 0;
        __syncthreads();
        s[tid] += t;
        __syncthreads();
    }
    int incl = s[tid];
    if (tid == 0) {
        unsigned int aggregate = (unsigned int)s[1023];
        atomicExch(&gz.agg[bid], aggregate | 0x80000000u);
    }
    if (tid < 32) {
        unsigned int sum = 0;
        for (int b = tid; b < bid; b += 32) {
            unsigned int a;
            do { a = *(volatile unsigned int*)&gz.agg[b]; } while (!(a & 0x80000000u));
            sum += a & 0x7fffffffu;
        }
        #pragma unroll
        for (int off = 16; off; off >>= 1) sum += __shfl_xor_sync(0xffffffffu, sum, off);
        if (tid == 0) sprefix = (int)sum;
    }
    __syncthreads();
    if (i < NN) {
        int o = sprefix + incl - v;   // exclusive global offset
        g_off[i] = o;
        g_cur[i] = o;
    }
}

// scatter with FUSED Ax SpMV: while placing each edge record, also
// REDG-accumulate norm * x[src] into ax[dst]. This deletes the separate
// warp-per-node k_ax pass (and its full edge-array re-read).
__global__ void k_scatter(const int* __restrict__ row, const int* __restrict__ colv,
                          const float* __restrict__ ew, const float* __restrict__ x) {
    int e = blockIdx.x*blockDim.x + threadIdx.x;
    if (e < EE) {
        int r = row[e], c = colv[e];
        float nm = g_dis[r] * ew[e] * g_dis[c];
        int p = atomicAdd(&g_cur[c], 1);
        unsigned long long pk =
            (((unsigned long long)(unsigned int)__float_as_int(nm)) << 32) | (unsigned int)r;
        g_edge[p] = pk;
        atomicAdd(&gz.ax[c], nm * __ldg(&x[r]));
    }
}

// ---------------- conv1 ----------------
// feat layout per node: 16 uint2 chunks (12 used, 128B record, 128B-aligned);
// chunk ch = cidx*3 + k holds fp16 features [4*cidx .. 4*cidx+3] of stack k.
__device__ __forceinline__ uint2 pack4h(float a, float b, float c, float d) {
    __half2 lo = __floats2half2_rn(a, b);
    __half2 hi = __floats2half2_rn(c, d);
    uint2 o;
    o.x = *(unsigned int*)&lo;
    o.y = *(unsigned int*)&hi;
    return o;
}

// node-parallel feat0 init: feat0 = relu(Ax*iw + x*rw + b); all 12 uint2
// stores land in the node's single 128B line.
__global__ void k_feat(const float* __restrict__ x, const float* __restrict__ iw,
                       const float* __restrict__ rw, const float* __restrict__ bs) {
    int n = blockIdx.x*blockDim.x + threadIdx.x;
    if (n >= NN) return;
    float s = gz.ax[n];
    float xv = __ldg(&x[n]);
    #pragma unroll
    for (int k = 0; k < 3; k++) {
        #pragma unroll
        for (int cidx = 0; cidx < 4; cidx++) {
            int f = k*16 + cidx*4;
            float f0 = fmaxf(s*__ldg(&iw[f+0]) + xv*__ldg(&rw[f+0]) + __ldg(&bs[f+0]), 0.f);
            float f1 = fmaxf(s*__ldg(&iw[f+1]) + xv*__ldg(&rw[f+1]) + __ldg(&bs[f+1]), 0.f);
            float f2 = fmaxf(s*__ldg(&iw[f+2]) + xv*__ldg(&rw[f+2]) + __ldg(&bs[f+2]), 0.f);
            float f3 = fmaxf(s*__ldg(&iw[f+3]) + xv*__ldg(&rw[f+3]) + __ldg(&bs[f+3]), 0.f);
            g_fa[n*16 + cidx*3 + k] = pack4h(f0, f1, f2, f3);
        }
    }
}

// Warp per node, dual-edge halves, unroll-4 pipelined fp16 gather.
// Per edge the 12 lanes load 96 contiguous bytes inside a 128B-aligned record.
// fp32 accumulate; epilogue: shfl-combine halves, smem exchange, fused
// 16x16 W matmul + root + relu. finalMode fuses mean/BN/relu + conv2 Horner prep.
__global__ void __launch_bounds__(256)
k_iter1(int srcIsB, int finalMode,
        const float* __restrict__ x, const float* __restrict__ w,
        const float* __restrict__ rw, const float* __restrict__ bs,
        const float* __restrict__ bng, const float* __restrict__ bnb,
        const float* __restrict__ bnm, const float* __restrict__ bnv,
        const float* __restrict__ iw2, const float* __restrict__ w2,
        const float* __restrict__ rw2, const float* __restrict__ b2) {
    __shared__ float wsh[768];
    __shared__ float rwsh[48], bsh[48];
    __shared__ float ex[8][56];
    for (int i = threadIdx.x; i < 768; i += 256) wsh[i] = w[i];
    if (threadIdx.x < 48) { rwsh[threadIdx.x] = rw[threadIdx.x]; bsh[threadIdx.x] = bs[threadIdx.x]; }
    __syncthreads();

    int warp = threadIdx.x >> 5;
    int lane = threadIdx.x & 31;
    int h = lane >> 4, c = lane & 15;
    bool act = c < 12;
    int n = blockIdx.x*8 + warp;                 // grid exact
    int st = g_off[n], cn = g_cnt[n];
    int e_end = st + cn;
    const uint2* F = srcIsB ? g_fb : g_fa;
    uint2*       D = srcIsB ? g_fa : g_fb;

    float4 acc = make_float4(0.f, 0.f, 0.f, 0.f);
    int j = st + h;
    while (j + 6 < e_end) {
        unsigned long long p0 = g_edge[j];
        unsigned long long p1 = g_edge[j+2];
        unsigned long long p2 = g_edge[j+4];
        unsigned long long p3 = g_edge[j+6];
        float m0 = __int_as_float((int)(p0 >> 32));
        float m1 = __int_as_float((int)(p1 >> 32));
        float m2 = __int_as_float((int)(p2 >> 32));
        float m3 = __int_as_float((int)(p3 >> 32));
        int s0 = (int)(p0 & 0xffffffffu);
        int s1 = (int)(p1 & 0xffffffffu);
        int s2 = (int)(p2 & 0xffffffffu);
        int s3 = (int)(p3 & 0xffffffffu);
        if (act) {
            uint2 q0 = __ldg(&F[s0*16 + c]);
            uint2 q1 = __ldg(&F[s1*16 + c]);
            uint2 q2 = __ldg(&F[s2*16 + c]);
            uint2 q3 = __ldg(&F[s3*16 + c]);
            float2 a0 = __half22float2(*(const __half2*)&q0.x);
            float2 b0 = __half22float2(*(const __half2*)&q0.y);
            float2 a1 = __half22float2(*(const __half2*)&q1.x);
            float2 b1 = __half22float2(*(const __half2*)&q1.y);
            float2 a2 = __half22float2(*(const __half2*)&q2.x);
            float2 b2v = __half22float2(*(const __half2*)&q2.y);
            float2 a3 = __half22float2(*(const __half2*)&q3.x);
            float2 b3 = __half22float2(*(const __half2*)&q3.y);
            acc.x += m0*a0.x + m1*a1.x + m2*a2.x + m3*a3.x;
            acc.y += m0*a0.y + m1*a1.y + m2*a2.y + m3*a3.y;
            acc.z += m0*b0.x + m1*b1.x + m2*b2v.x + m3*b3.x;
            acc.w += m0*b0.y + m1*b1.y + m2*b2v.y + m3*b3.y;
        }
        j += 8;
    }
    while (j < e_end) {
        unsigned long long p0 = g_edge[j];
        float m0 = __int_as_float((int)(p0 >> 32));
        int s0 = (int)(p0 & 0xffffffffu);
        if (act) {
            uint2 q0 = __ldg(&F[s0*16 + c]);
            float2 a0 = __half22float2(*(const __half2*)&q0.x);
            float2 b0 = __half22float2(*(const __half2*)&q0.y);
            acc.x += m0*a0.x; acc.y += m0*a0.y; acc.z += m0*b0.x; acc.w += m0*b0.y;
        }
        j += 2;
    }

    // combine the two halves
    acc.x += __shfl_xor_sync(0xffffffffu, acc.x, 16);
    acc.y += __shfl_xor_sync(0xffffffffu, acc.y, 16);
    acc.z += __shfl_xor_sync(0xffffffffu, acc.z, 16);
    acc.w += __shfl_xor_sync(0xffffffffu, acc.w, 16);

    int kk = c % 3, cidx = c / 3;   // chunk c = cidx*3 + kk
    bool act0 = (h == 0) && act;
    if (act0) {
        float* e = ex[warp] + kk*16 + cidx*4;
        e[0] = acc.x; e[1] = acc.y; e[2] = acc.z; e[3] = acc.w;
    }
    __syncwarp();

    // y = af * W[k] + x*root_w + bias, relu  (A(out)w == A(out w))
    float4 yv = make_float4(0.f, 0.f, 0.f, 0.f);
    if (act0) {
        const float* af = ex[warp] + kk*16;
        const float* wk = wsh + kk*256;
        float xv = __ldg(&x[n]);
        float* py = (float*)&yv;
        #pragma unroll
        for (int i = 0; i < 4; i++) {
            int oo = cidx*4 + i;
            float y = 0.f;
            #pragma unroll
            for (int f = 0; f < 16; f++) y += af[f] * wk[f*16 + oo];
            py[i] = fmaxf(y + xv*rwsh[kk*16+oo] + bsh[kk*16+oo], 0.f);
        }
    }
    __syncwarp();

    if (!finalMode) {
        if (act0) D[n*16 + c] = pack4h(yv.x, yv.y, yv.z, yv.w);
        return;
    }

    // ---- final iteration: mean over stacks + BN + relu + conv2 Horner prep ----
    if (act0) {
        float* e = ex[warp] + kk*16 + cidx*4;
        e[0] = yv.x; e[1] = yv.y; e[2] = yv.z; e[3] = yv.w;
    }
    __syncwarp();
    if (lane < 16) {
        float m = (ex[warp][lane] + ex[warp][16+lane] + ex[warp][32+lane]) * (1.f/3.f);
        float sc = __ldg(&bng[lane]) * rsqrtf(__ldg(&bnv[lane]) + 1e-5f);
        ex[warp][lane] = fmaxf((m - __ldg(&bnm[lane]))*sc + __ldg(&bnb[lane]), 0.f);
    }
    __syncwarp();
    if (lane == 0) {
        float hv[16];
        #pragma unroll
        for (int f = 0; f < 16; f++) hv[f] = ex[warp][f];
        float o[3] = {0,0,0}, r[3] = {0,0,0};
        #pragma unroll
        for (int k2 = 0; k2 < 3; k2++) {
            #pragma unroll
            for (int f = 0; f < 16; f++) {
                o[k2] += hv[f] * __ldg(&iw2[k2*16+f]);
                r[k2] += hv[f] * __ldg(&rw2[k2*16+f]);
            }
            r[k2] += __ldg(&b2[k2]);
        }
        float z = 0.f, s3v = 0.f, s2v = 0.f, s1v = 0.f, s0v = 0.f;
        #pragma unroll
        for (int k2 = 0; k2 < 3; k2++) {
            float wv = __ldg(&w2[k2]);
            float w2p = wv*wv, w3p = w2p*wv;
            z   += w3p * o[k2];
            s3v += w3p * r[k2];
            s2v += w2p * r[k2];
            s1v += wv  * r[k2];
            s0v += r[k2];
        }
        g_ca[n] = z;
        float4 sv; sv.x = s3v; sv.y = s2v; sv.z = s1v; sv.w = s0v;
        g_s[n] = sv;
    }
}

// ---------------- conv2: 4 scalar Horner SpMV passes ----------------
// result = sigmoid( (A(A(A(A z + s3) + s2) + s1) + s0) / 3 )
// Half-warp per node: 2 nodes/warp, 4-level shuffle reduce.
__global__ void __launch_bounds__(256)
k_sp(int pass, float* __restrict__ finalOut) {
    int n = (blockIdx.x*256 + threadIdx.x) >> 4;   // grid exact: 6250*16 = 100000
    int lane = threadIdx.x & 15;
    int st = g_off[n], cn = g_cnt[n];
    const float* src = (pass & 1) ? g_cb : g_ca;
    float s = 0.f;
    for (int j = st + lane; j < st + cn; j += 16) {
        unsigned long long pk = g_edge[j];
        s += __int_as_float((int)(pk >> 32)) * __ldg(&src[(int)(pk & 0xffffffffu)]);
    }
    #pragma unroll
    for (int off = 8; off; off >>= 1) s += __shfl_xor_sync(0xffffffffu, s, off);
    if (lane == 0) {
        float4 sv = __ldg(&g_s[n]);
        float si = (pass == 0) ? sv.x : (pass == 1) ? sv.y : (pass == 2) ? sv.z : sv.w;
        float cval = s + si;
        if (pass == 3) {
            finalOut[n] = 1.f / (1.f + expf(-cval * (1.f/3.f)));
        } else {
            float* dst = (pass & 1) ? g_ca : g_cb;
            dst[n] = cval;
        }
    }
}

// ---------------- driver ----------------
extern "C" void kernel_launch(void* const* d_in, const int* in_sizes, int n_in,
                              void* d_out, int out_size) {
    const float* x    = (const float*)d_in[0];
    const int*   ei   = (const int*)  d_in[1];
    const float* ew   = (const float*)d_in[2];
    const float* c1iw = (const float*)d_in[3];
    const float* c1w  = (const float*)d_in[4];
    const float* c1rw = (const float*)d_in[5];
    const float* c1b  = (const float*)d_in[6];
    const float* bng  = (const float*)d_in[7];
    const float* bnb  = (const float*)d_in[8];
    const float* bnm  = (const float*)d_in[9];
    const float* bnv  = (const float*)d_in[10];
    const float* c2iw = (const float*)d_in[11];
    const float* c2w  = (const float*)d_in[12];
    const float* c2rw = (const float*)d_in[13];
    const float* c2b  = (const float*)d_in[14];
    float* out = (float*)d_out;

    const int* row = ei;
    const int* col = ei + EE;

    const int EG = (EE + 255) / 256;
    const int NG = (NN + 255) / 256;
    const int WG = 12500;   // warp-per-node: 12500 blocks x 8 warps = 100000
    const int HG = 6250;    // half-warp-per-node: 6250 blocks x 16 halves = 100000

    // zero packed deg/cnt + ax + lookback aggregates in one memset node
    void* zp = nullptr;
    cudaGetSymbolAddress(&zp, gz);
    cudaMemsetAsync(zp, 0, sizeof(ZBlock), 0);

    // gcn_norm + CSR build; scatter fuses the rank-1 Ax SpMV via REDG
    k_deg<<<EG, 256>>>(col, ew);
    k_scan<<<NBLK, 1024>>>();
    k_scatter<<<EG, 256>>>(row, col, ew, x);

    // conv1: node-parallel feat0 init, then 3 fp16 SpMM iterations
    k_feat<<<NG, 256>>>(x, c1iw, c1rw, c1b);                                                 // (Ax,x) -> fa
    k_iter1<<<WG, 256>>>(0, 0, x, c1w, c1rw, c1b, bng, bnb, bnm, bnv, c2iw, c2w, c2rw, c2b); // fa -> fb
    k_iter1<<<WG, 256>>>(1, 0, x, c1w, c1rw, c1b, bng, bnb, bnm, bnv, c2iw, c2w, c2rw, c2b); // fb -> fa
    k_iter1<<<WG, 256>>>(0, 1, x, c1w, c1rw, c1b, bng, bnb, bnm, bnv, c2iw, c2w, c2rw, c2b); // fa -> Horner prep

    // conv2: 4 scalar Horner passes, last fuses sigmoid -> out
    k_sp<<<HG, 256>>>(0, nullptr);  // ca -> cb  (+s3)
    k_sp<<<HG, 256>>>(1, nullptr);  // cb -> ca  (+s2)
    k_sp<<<HG, 256>>>(2, nullptr);  // ca -> cb  (+s1)
    k_sp<<<HG, 256>>>(3, out);      // cb -> sigmoid((c+s0)/3) -> out
}

// round 12
// speedup vs baseline: 1.0803x; 1.0415x over previous
#include <cuda_runtime.h>
#include <cuda_fp16.h>
#include <math.h>

#define NN 100000
#define EE 3200000
#define NBLK 98   // ceil(NN/1024)

// ---------------- scratch (device globals; no runtime allocation) ----------------
// zeroed each run by one cudaMemsetAsync (memset node in the graph)
struct ZBlock {
    unsigned long long pk[NN];  // {count:24bits | fixed-point weight sum:40bits}
    unsigned int agg[NBLK];     // decoupled-lookback aggregates (bit31 = ready)
};
__device__ ZBlock gz;

__device__ float g_dis[NN];
__device__ int   g_cnt[NN];
__device__ int   g_off[NN];
__device__ int   g_cur[NN];
__device__ unsigned long long g_edge[EE];     // packed {norm:f32 (hi), src:i32 (lo)}
__device__ __align__(16) uint2 g_fa[NN*16];   // conv1 fp16 feats ping (12 of 16 chunks; 128B/node)
__device__ __align__(16) uint2 g_fb[NN*16];   // conv1 fp16 feats pong
__device__ float g_ca[NN];                    // conv2 Horner scalar, ping
__device__ float g_cb[NN];                    // conv2 Horner scalar, pong
__device__ __align__(16) float4 g_s[NN];      // (s3, s2, s1, s0) per node

// ---------------- gcn_norm + CSR build ----------------
// ONE packed 64-bit fire-and-forget atomic per edge: high 24 bits count,
// low 40 bits fixed-point (2^-28) sum of edge weights.
__global__ void k_deg(const int* __restrict__ col, const float* __restrict__ ew) {
    int e = blockIdx.x*blockDim.x + threadIdx.x;
    if (e < EE) {
        unsigned long long inc = (1ull << 40) |
            (unsigned long long)(ew[e] * 268435456.f + 0.5f);
        atomicAdd(&gz.pk[col[e]], inc);
    }
}

// fused: unpack deg/cnt + dis + block scan + decoupled lookback + offsets
__global__ void __launch_bounds__(1024) k_scan() {
    __shared__ int s[1024];
    __shared__ int sprefix;
    int tid = threadIdx.x, bid = blockIdx.x;
    int i = bid*1024 + tid;
    int v = 0;
    if (i < NN) {
        unsigned long long p = gz.pk[i];
        v = (int)(p >> 40);
        float d = (float)(p & 0xFFFFFFFFFFull) * 3.7252902984619141e-09f; // 2^-28
        g_dis[i] = d > 0.f ? rsqrtf(fmaxf(d, 1e-12f)) : 0.f;
        g_cnt[i] = v;
    }
    s[tid] = v;
    __syncthreads();
    for (int off = 1; off < 1024; off <<= 1) {
        int t = (tid >= off) ? s[tid - off] : 0;
        __syncthreads();
        s[tid] += t;
        __syncthreads();
    }
    int incl = s[tid];
    if (tid == 0) {
        unsigned int aggregate = (unsigned int)s[1023];
        atomicExch(&gz.agg[bid], aggregate | 0x80000000u);
    }
    if (tid < 32) {
        unsigned int sum = 0;
        for (int b = tid; b < bid; b += 32) {
            unsigned int a;
            do { a = *(volatile unsigned int*)&gz.agg[b]; } while (!(a & 0x80000000u));
            sum += a & 0x7fffffffu;
        }
        #pragma unroll
        for (int off = 16; off; off >>= 1) sum += __shfl_xor_sync(0xffffffffu, sum, off);
        if (tid == 0) sprefix = (int)sum;
    }
    __syncthreads();
    if (i < NN) {
        int o = sprefix + incl - v;   // exclusive global offset
        g_off[i] = o;
        g_cur[i] = o;
    }
}

__global__ void k_scatter(const int* __restrict__ row, const int* __restrict__ colv,
                          const float* __restrict__ ew) {
    int e = blockIdx.x*blockDim.x + threadIdx.x;
    if (e < EE) {
        int r = row[e], c = colv[e];
        float nm = g_dis[r] * ew[e] * g_dis[c];
        int p = atomicAdd(&g_cur[c], 1);
        unsigned long long pk =
            (((unsigned long long)(unsigned int)__float_as_int(nm)) << 32) | (unsigned int)r;
        g_edge[p] = pk;
    }
}

// ---------------- conv1 ----------------
// feat layout per node: 16 uint2 chunks (12 used, 128B record, 128B-aligned);
// chunk ch = cidx*3 + k holds fp16 features [4*cidx .. 4*cidx+3] of stack k.
__device__ __forceinline__ uint2 pack4h(float a, float b, float c, float d) {
    __half2 lo = __floats2half2_rn(a, b);
    __half2 hi = __floats2half2_rn(c, d);
    uint2 o;
    o.x = *(unsigned int*)&lo;
    o.y = *(unsigned int*)&hi;
    return o;
}

// Warp per node: lanes stride over edges (unroll-2 for MLP), shuffle-reduce Ax,
// then lanes 0..11 write the initial fp16 feature state.
__global__ void __launch_bounds__(256)
k_ax(const float* __restrict__ x, const float* __restrict__ iw,
     const float* __restrict__ rw, const float* __restrict__ bs) {
    int n = (blockIdx.x*256 + threadIdx.x) >> 5;   // grid exact: 12500*8 = 100000
    int lane = threadIdx.x & 31;
    int st = g_off[n], cn = g_cnt[n];
    int e_end = st + cn;
    float s = 0.f;
    int j = st + lane;
    for (; j + 32 < e_end; j += 64) {
        unsigned long long p0 = g_edge[j];
        unsigned long long p1 = g_edge[j+32];
        s += __int_as_float((int)(p0 >> 32)) * __ldg(&x[(int)(p0 & 0xffffffffu)]);
        s += __int_as_float((int)(p1 >> 32)) * __ldg(&x[(int)(p1 & 0xffffffffu)]);
    }
    if (j < e_end) {
        unsigned long long p0 = g_edge[j];
        s += __int_as_float((int)(p0 >> 32)) * __ldg(&x[(int)(p0 & 0xffffffffu)]);
    }
    #pragma unroll
    for (int off = 16; off; off >>= 1) s += __shfl_xor_sync(0xffffffffu, s, off);
    float xv = __ldg(&x[n]);
    if (lane < 12) {
        int k = lane % 3, cidx = lane / 3;
        int f = k*16 + cidx*4;
        float f0 = fmaxf(s*__ldg(&iw[f+0]) + xv*__ldg(&rw[f+0]) + __ldg(&bs[f+0]), 0.f);
        float f1 = fmaxf(s*__ldg(&iw[f+1]) + xv*__ldg(&rw[f+1]) + __ldg(&bs[f+1]), 0.f);
        float f2 = fmaxf(s*__ldg(&iw[f+2]) + xv*__ldg(&rw[f+2]) + __ldg(&bs[f+2]), 0.f);
        float f3 = fmaxf(s*__ldg(&iw[f+3]) + xv*__ldg(&rw[f+3]) + __ldg(&bs[f+3]), 0.f);
        g_fa[n*16 + cidx*3 + k] = pack4h(f0, f1, f2, f3);
    }
}

// Warp per node, dual-edge halves, unroll-4 pipelined fp16 gather.
// Per edge the 12 lanes load 96 contiguous bytes inside a 128B-aligned record.
// fp32 accumulate; epilogue: shfl-combine halves, smem exchange, fused
// 16x16 W matmul + root + relu. finalMode fuses mean/BN/relu + conv2 Horner prep.
__global__ void __launch_bounds__(256)
k_iter1(int srcIsB, int finalMode,
        const float* __restrict__ x, const float* __restrict__ w,
        const float* __restrict__ rw, const float* __restrict__ bs,
        const float* __restrict__ bng, const float* __restrict__ bnb,
        const float* __restrict__ bnm, const float* __restrict__ bnv,
        const float* __restrict__ iw2, const float* __restrict__ w2,
        const float* __restrict__ rw2, const float* __restrict__ b2) {
    __shared__ float wsh[768];
    __shared__ float rwsh[48], bsh[48];
    __shared__ float ex[8][56];
    for (int i = threadIdx.x; i < 768; i += 256) wsh[i] = w[i];
    if (threadIdx.x < 48) { rwsh[threadIdx.x] = rw[threadIdx.x]; bsh[threadIdx.x] = bs[threadIdx.x]; }
    __syncthreads();

    int warp = threadIdx.x >> 5;
    int lane = threadIdx.x & 31;
    int h = lane >> 4, c = lane & 15;
    bool act = c < 12;
    int n = blockIdx.x*8 + warp;                 // grid exact
    int st = g_off[n], cn = g_cnt[n];
    int e_end = st + cn;
    const uint2* F = srcIsB ? g_fb : g_fa;
    uint2*       D = srcIsB ? g_fa : g_fb;

    float4 acc = make_float4(0.f, 0.f, 0.f, 0.f);
    int j = st + h;
    while (j + 6 < e_end) {
        unsigned long long p0 = g_edge[j];
        unsigned long long p1 = g_edge[j+2];
        unsigned long long p2 = g_edge[j+4];
        unsigned long long p3 = g_edge[j+6];
        float m0 = __int_as_float((int)(p0 >> 32));
        float m1 = __int_as_float((int)(p1 >> 32));
        float m2 = __int_as_float((int)(p2 >> 32));
        float m3 = __int_as_float((int)(p3 >> 32));
        int s0 = (int)(p0 & 0xffffffffu);
        int s1 = (int)(p1 & 0xffffffffu);
        int s2 = (int)(p2 & 0xffffffffu);
        int s3 = (int)(p3 & 0xffffffffu);
        if (act) {
            uint2 q0 = __ldg(&F[s0*16 + c]);
            uint2 q1 = __ldg(&F[s1*16 + c]);
            uint2 q2 = __ldg(&F[s2*16 + c]);
            uint2 q3 = __ldg(&F[s3*16 + c]);
            float2 a0 = __half22float2(*(const __half2*)&q0.x);
            float2 b0 = __half22float2(*(const __half2*)&q0.y);
            float2 a1 = __half22float2(*(const __half2*)&q1.x);
            float2 b1 = __half22float2(*(const __half2*)&q1.y);
            float2 a2 = __half22float2(*(const __half2*)&q2.x);
            float2 b2v = __half22float2(*(const __half2*)&q2.y);
            float2 a3 = __half22float2(*(const __half2*)&q3.x);
            float2 b3 = __half22float2(*(const __half2*)&q3.y);
            acc.x += m0*a0.x + m1*a1.x + m2*a2.x + m3*a3.x;
            acc.y += m0*a0.y + m1*a1.y + m2*a2.y + m3*a3.y;
            acc.z += m0*b0.x + m1*b1.x + m2*b2v.x + m3*b3.x;
            acc.w += m0*b0.y + m1*b1.y + m2*b2v.y + m3*b3.y;
        }
        j += 8;
    }
    while (j < e_end) {
        unsigned long long p0 = g_edge[j];
        float m0 = __int_as_float((int)(p0 >> 32));
        int s0 = (int)(p0 & 0xffffffffu);
        if (act) {
            uint2 q0 = __ldg(&F[s0*16 + c]);
            float2 a0 = __half22float2(*(const __half2*)&q0.x);
            float2 b0 = __half22float2(*(const __half2*)&q0.y);
            acc.x += m0*a0.x; acc.y += m0*a0.y; acc.z += m0*b0.x; acc.w += m0*b0.y;
        }
        j += 2;
    }

    // combine the two halves
    acc.x += __shfl_xor_sync(0xffffffffu, acc.x, 16);
    acc.y += __shfl_xor_sync(0xffffffffu, acc.y, 16);
    acc.z += __shfl_xor_sync(0xffffffffu, acc.z, 16);
    acc.w += __shfl_xor_sync(0xffffffffu, acc.w, 16);

    int kk = c % 3, cidx = c / 3;   // chunk c = cidx*3 + kk
    bool act0 = (h == 0) && act;
    if (act0) {
        float* e = ex[warp] + kk*16 + cidx*4;
        e[0] = acc.x; e[1] = acc.y; e[2] = acc.z; e[3] = acc.w;
    }
    __syncwarp();

    // y = af * W[k] + x*root_w + bias, relu  (A(out)w == A(out w))
    float4 yv = make_float4(0.f, 0.f, 0.f, 0.f);
    if (act0) {
        const float* af = ex[warp] + kk*16;
        const float* wk = wsh + kk*256;
        float xv = __ldg(&x[n]);
        float* py = (float*)&yv;
        #pragma unroll
        for (int i = 0; i < 4; i++) {
            int oo = cidx*4 + i;
            float y = 0.f;
            #pragma unroll
            for (int f = 0; f < 16; f++) y += af[f] * wk[f*16 + oo];
            py[i] = fmaxf(y + xv*rwsh[kk*16+oo] + bsh[kk*16+oo], 0.f);
        }
    }
    __syncwarp();

    if (!finalMode) {
        if (act0) D[n*16 + c] = pack4h(yv.x, yv.y, yv.z, yv.w);
        return;
    }

    // ---- final iteration: mean over stacks + BN + relu + conv2 Horner prep ----
    if (act0) {
        float* e = ex[warp] + kk*16 + cidx*4;
        e[0] = yv.x; e[1] = yv.y; e[2] = yv.z; e[3] = yv.w;
    }
    __syncwarp();
    if (lane < 16) {
        float m = (ex[warp][lane] + ex[warp][16+lane] + ex[warp][32+lane]) * (1.f/3.f);
        float sc = __ldg(&bng[lane]) * rsqrtf(__ldg(&bnv[lane]) + 1e-5f);
        ex[warp][lane] = fmaxf((m - __ldg(&bnm[lane]))*sc + __ldg(&bnb[lane]), 0.f);
    }
    __syncwarp();
    if (lane == 0) {
        float hv[16];
        #pragma unroll
        for (int f = 0; f < 16; f++) hv[f] = ex[warp][f];
        float o[3] = {0,0,0}, r[3] = {0,0,0};
        #pragma unroll
        for (int k2 = 0; k2 < 3; k2++) {
            #pragma unroll
            for (int f = 0; f < 16; f++) {
                o[k2] += hv[f] * __ldg(&iw2[k2*16+f]);
                r[k2] += hv[f] * __ldg(&rw2[k2*16+f]);
            }
            r[k2] += __ldg(&b2[k2]);
        }
        float z = 0.f, s3v = 0.f, s2v = 0.f, s1v = 0.f, s0v = 0.f;
        #pragma unroll
        for (int k2 = 0; k2 < 3; k2++) {
            float wv = __ldg(&w2[k2]);
            float w2p = wv*wv, w3p = w2p*wv;
            z   += w3p * o[k2];
            s3v += w3p * r[k2];
            s2v += w2p * r[k2];
            s1v += wv  * r[k2];
            s0v += r[k2];
        }
        g_ca[n] = z;
        float4 sv; sv.x = s3v; sv.y = s2v; sv.z = s1v; sv.w = s0v;
        g_s[n] = sv;
    }
}

// ---------------- conv2: 4 scalar Horner SpMV passes ----------------
// result = sigmoid( (A(A(A(A z + s3) + s2) + s1) + s0) / 3 )
// Half-warp per node: 2 nodes/warp, unroll-2 edge loop, 4-level shuffle reduce.
__global__ void __launch_bounds__(256)
k_sp(int pass, float* __restrict__ finalOut) {
    int n = (blockIdx.x*256 + threadIdx.x) >> 4;   // grid exact: 6250*16 = 100000
    int lane = threadIdx.x & 15;
    int st = g_off[n], cn = g_cnt[n];
    int e_end = st + cn;
    const float* src = (pass & 1) ? g_cb : g_ca;
    float s = 0.f;
    int j = st + lane;
    for (; j + 16 < e_end; j += 32) {
        unsigned long long p0 = g_edge[j];
        unsigned long long p1 = g_edge[j+16];
        s += __int_as_float((int)(p0 >> 32)) * __ldg(&src[(int)(p0 & 0xffffffffu)]);
        s += __int_as_float((int)(p1 >> 32)) * __ldg(&src[(int)(p1 & 0xffffffffu)]);
    }
    if (j < e_end) {
        unsigned long long p0 = g_edge[j];
        s += __int_as_float((int)(p0 >> 32)) * __ldg(&src[(int)(p0 & 0xffffffffu)]);
    }
    #pragma unroll
    for (int off = 8; off; off >>= 1) s += __shfl_xor_sync(0xffffffffu, s, off);
    if (lane == 0) {
        float4 sv = __ldg(&g_s[n]);
        float si = (pass == 0) ? sv.x : (pass == 1) ? sv.y : (pass == 2) ? sv.z : sv.w;
        float cval = s + si;
        if (pass == 3) {
            finalOut[n] = 1.f / (1.f + expf(-cval * (1.f/3.f)));
        } else {
            float* dst = (pass & 1) ? g_ca : g_cb;
            dst[n] = cval;
        }
    }
}

// ---------------- driver ----------------
extern "C" void kernel_launch(void* const* d_in, const int* in_sizes, int n_in,
                              void* d_out, int out_size) {
    const float* x    = (const float*)d_in[0];
    const int*   ei   = (const int*)  d_in[1];
    const float* ew   = (const float*)d_in[2];
    const float* c1iw = (const float*)d_in[3];
    const float* c1w  = (const float*)d_in[4];
    const float* c1rw = (const float*)d_in[5];
    const float* c1b  = (const float*)d_in[6];
    const float* bng  = (const float*)d_in[7];
    const float* bnb  = (const float*)d_in[8];
    const float* bnm  = (const float*)d_in[9];
    const float* bnv  = (const float*)d_in[10];
    const float* c2iw = (const float*)d_in[11];
    const float* c2w  = (const float*)d_in[12];
    const float* c2rw = (const float*)d_in[13];
    const float* c2b  = (const float*)d_in[14];
    float* out = (float*)d_out;

    const int* row = ei;
    const int* col = ei + EE;

    const int EG = (EE + 255) / 256;
    const int WG = 12500;   // warp-per-node: 12500 blocks x 8 warps = 100000
    const int HG = 6250;    // half-warp-per-node: 6250 blocks x 16 halves = 100000

    // zero packed deg/cnt + lookback aggregates in one memset node
    void* zp = nullptr;
    cudaGetSymbolAddress(&zp, gz);
    cudaMemsetAsync(zp, 0, sizeof(ZBlock), 0);

    // gcn_norm + CSR build
    k_deg<<<EG, 256>>>(col, ew);
    k_scan<<<NBLK, 1024>>>();
    k_scatter<<<EG, 256>>>(row, col, ew);

    // conv1: rank-1 first propagation (+fused feature init), then 3 SpMM iters
    k_ax<<<WG, 256>>>(x, c1iw, c1rw, c1b);
    k_iter1<<<WG, 256>>>(0, 0, x, c1w, c1rw, c1b, bng, bnb, bnm, bnv, c2iw, c2w, c2rw, c2b); // fa -> fb
    k_iter1<<<WG, 256>>>(1, 0, x, c1w, c1rw, c1b, bng, bnb, bnm, bnv, c2iw, c2w, c2rw, c2b); // fb -> fa
    k_iter1<<<WG, 256>>>(0, 1, x, c1w, c1rw, c1b, bng, bnb, bnm, bnv, c2iw, c2w, c2rw, c2b); // fa -> Horner prep

    // conv2: 4 scalar Horner passes, last fuses sigmoid -> out
    k_sp<<<HG, 256>>>(0, nullptr);  // ca -> cb  (+s3)
    k_sp<<<HG, 256>>>(1, nullptr);  // cb -> ca  (+s2)
    k_sp<<<HG, 256>>>(2, nullptr);  // ca -> cb  (+s1)
    k_sp<<<HG, 256>>>(3, out);      // cb -> sigmoid((c+s0)/3) -> out
}

// round 13
// speedup vs baseline: 1.1297x; 1.0457x over previous
#include <cuda_runtime.h>
#include <cuda_fp16.h>
#include <math.h>

#define NN 100000
#define EE 3200000
#define NBLK 98   // ceil(NN/1024)

// ---------------- scratch (device globals; no runtime allocation) ----------------
// zeroed each run by one cudaMemsetAsync (memset node in the graph)
struct ZBlock {
    unsigned long long pk[NN];  // {count:24bits | fixed-point weight sum:40bits}
    unsigned int agg[NBLK];     // decoupled-lookback aggregates (bit31 = ready)
};
__device__ ZBlock gz;

__device__ float g_dis[NN];
__device__ int   g_cnt[NN];
__device__ int   g_off[NN];
__device__ int   g_cur[NN];
__device__ unsigned int g_edge[EE];           // packed {norm:fp16-sans-sign [31:17] | src:17 [16:0]}
__device__ __align__(16) uint2 g_fa[NN*16];   // conv1 fp16 feats ping (12 of 16 chunks; 128B/node)
__device__ __align__(16) uint2 g_fb[NN*16];   // conv1 fp16 feats pong
__device__ float g_ca[NN];                    // conv2 Horner scalar, ping
__device__ float g_cb[NN];                    // conv2 Horner scalar, pong
__device__ __align__(16) float4 g_s[NN];      // (s3, s2, s1, s0) per node

__device__ __forceinline__ float dnorm(unsigned int u) {
    return __half2float(__ushort_as_half((unsigned short)(u >> 17)));
}
__device__ __forceinline__ int dsrc(unsigned int u) { return (int)(u & 0x1ffffu); }

// ---------------- gcn_norm + CSR build ----------------
// ONE packed 64-bit fire-and-forget atomic per edge: high 24 bits count,
// low 40 bits fixed-point (2^-28) sum of edge weights.
__global__ void k_deg(const int* __restrict__ col, const float* __restrict__ ew) {
    int e = blockIdx.x*blockDim.x + threadIdx.x;
    if (e < EE) {
        unsigned long long inc = (1ull << 40) |
            (unsigned long long)(ew[e] * 268435456.f + 0.5f);
        atomicAdd(&gz.pk[col[e]], inc);
    }
}

// fused: unpack deg/cnt + dis + block scan + decoupled lookback + offsets
__global__ void __launch_bounds__(1024) k_scan() {
    __shared__ int s[1024];
    __shared__ int sprefix;
    int tid = threadIdx.x, bid = blockIdx.x;
    int i = bid*1024 + tid;
    int v = 0;
    if (i < NN) {
        unsigned long long p = gz.pk[i];
        v = (int)(p >> 40);
        float d = (float)(p & 0xFFFFFFFFFFull) * 3.7252902984619141e-09f; // 2^-28
        g_dis[i] = d > 0.f ? rsqrtf(fmaxf(d, 1e-12f)) : 0.f;
        g_cnt[i] = v;
    }
    s[tid] = v;
    __syncthreads();
    for (int off = 1; off < 1024; off <<= 1) {
        int t = (tid >= off) ? s[tid - off] : 0;
        __syncthreads();
        s[tid] += t;
        __syncthreads();
    }
    int incl = s[tid];
    if (tid == 0) {
        unsigned int aggregate = (unsigned int)s[1023];
        atomicExch(&gz.agg[bid], aggregate | 0x80000000u);
    }
    if (tid < 32) {
        unsigned int sum = 0;
        for (int b = tid; b < bid; b += 32) {
            unsigned int a;
            do { a = *(volatile unsigned int*)&gz.agg[b]; } while (!(a & 0x80000000u));
            sum += a & 0x7fffffffu;
        }
        #pragma unroll
        for (int off = 16; off; off >>= 1) sum += __shfl_xor_sync(0xffffffffu, sum, off);
        if (tid == 0) sprefix = (int)sum;
    }
    __syncthreads();
    if (i < NN) {
        int o = sprefix + incl - v;   // exclusive global offset
        g_off[i] = o;
        g_cur[i] = o;
    }
}

__global__ void k_scatter(const int* __restrict__ row, const int* __restrict__ colv,
                          const float* __restrict__ ew) {
    int e = blockIdx.x*blockDim.x + threadIdx.x;
    if (e < EE) {
        int r = row[e], c = colv[e];
        float nm = g_dis[r] * ew[e] * g_dis[c];
        int p = atomicAdd(&g_cur[c], 1);
        unsigned short hb = __half_as_ushort(__float2half_rn(nm));  // nm >= 0, sign bit 0
        g_edge[p] = ((unsigned int)hb << 17) | (unsigned int)r;
    }
}

// ---------------- conv1 ----------------
// feat layout per node: 16 uint2 chunks (12 used, 128B record, 128B-aligned);
// chunk ch = cidx*3 + k holds fp16 features [4*cidx .. 4*cidx+3] of stack k.
__device__ __forceinline__ uint2 pack4h(float a, float b, float c, float d) {
    __half2 lo = __floats2half2_rn(a, b);
    __half2 hi = __floats2half2_rn(c, d);
    uint2 o;
    o.x = *(unsigned int*)&lo;
    o.y = *(unsigned int*)&hi;
    return o;
}

// Warp per node: lanes stride over edges (unroll-2 for MLP), shuffle-reduce Ax,
// then lanes 0..11 write the initial fp16 feature state.
__global__ void __launch_bounds__(256)
k_ax(const float* __restrict__ x, const float* __restrict__ iw,
     const float* __restrict__ rw, const float* __restrict__ bs) {
    int n = (blockIdx.x*256 + threadIdx.x) >> 5;   // grid exact: 12500*8 = 100000
    int lane = threadIdx.x & 31;
    int st = g_off[n], cn = g_cnt[n];
    int e_end = st + cn;
    float s = 0.f;
    int j = st + lane;
    for (; j + 32 < e_end; j += 64) {
        unsigned int u0 = g_edge[j];
        unsigned int u1 = g_edge[j+32];
        s += dnorm(u0) * __ldg(&x[dsrc(u0)]);
        s += dnorm(u1) * __ldg(&x[dsrc(u1)]);
    }
    if (j < e_end) {
        unsigned int u0 = g_edge[j];
        s += dnorm(u0) * __ldg(&x[dsrc(u0)]);
    }
    #pragma unroll
    for (int off = 16; off; off >>= 1) s += __shfl_xor_sync(0xffffffffu, s, off);
    float xv = __ldg(&x[n]);
    if (lane < 12) {
        int k = lane % 3, cidx = lane / 3;
        int f = k*16 + cidx*4;
        float f0 = fmaxf(s*__ldg(&iw[f+0]) + xv*__ldg(&rw[f+0]) + __ldg(&bs[f+0]), 0.f);
        float f1 = fmaxf(s*__ldg(&iw[f+1]) + xv*__ldg(&rw[f+1]) + __ldg(&bs[f+1]), 0.f);
        float f2 = fmaxf(s*__ldg(&iw[f+2]) + xv*__ldg(&rw[f+2]) + __ldg(&bs[f+2]), 0.f);
        float f3 = fmaxf(s*__ldg(&iw[f+3]) + xv*__ldg(&rw[f+3]) + __ldg(&bs[f+3]), 0.f);
        g_fa[n*16 + cidx*3 + k] = pack4h(f0, f1, f2, f3);
    }
}

// Warp per node, dual-edge halves, unroll-8 pipelined fp16 gather.
// Per edge the 12 lanes load 96 contiguous bytes inside a 128B-aligned record.
// fp32 accumulate; epilogue: shfl-combine halves, smem exchange, fused 16x16 W
// matmul spread over 24 lanes (2 outputs each) + root + relu. finalMode fuses
// mean/BN/relu + conv2 Horner prep.
__global__ void __launch_bounds__(256)
k_iter1(int srcIsB, int finalMode,
        const float* __restrict__ x, const float* __restrict__ w,
        const float* __restrict__ rw, const float* __restrict__ bs,
        const float* __restrict__ bng, const float* __restrict__ bnb,
        const float* __restrict__ bnm, const float* __restrict__ bnv,
        const float* __restrict__ iw2, const float* __restrict__ w2,
        const float* __restrict__ rw2, const float* __restrict__ b2) {
    __shared__ float wsh[768];
    __shared__ float rwsh[48], bsh[48];
    __shared__ float ex[8][56];
    for (int i = threadIdx.x; i < 768; i += 256) wsh[i] = w[i];
    if (threadIdx.x < 48) { rwsh[threadIdx.x] = rw[threadIdx.x]; bsh[threadIdx.x] = bs[threadIdx.x]; }
    __syncthreads();

    int warp = threadIdx.x >> 5;
    int lane = threadIdx.x & 31;
    int h = lane >> 4, c = lane & 15;
    bool act = c < 12;
    int n = blockIdx.x*8 + warp;                 // grid exact
    int st = g_off[n], cn = g_cnt[n];
    int e_end = st + cn;
    const uint2* F = srcIsB ? g_fb : g_fa;
    uint2*       D = srcIsB ? g_fa : g_fb;

    float4 acc = make_float4(0.f, 0.f, 0.f, 0.f);
    int j = st + h;

    #define ACCUM(q, m) { \
        float2 _a = __half22float2(*(const __half2*)&(q).x); \
        float2 _b = __half22float2(*(const __half2*)&(q).y); \
        acc.x += (m)*_a.x; acc.y += (m)*_a.y; acc.z += (m)*_b.x; acc.w += (m)*_b.y; }

    while (j + 14 < e_end) {
        unsigned int u0 = g_edge[j],    u1 = g_edge[j+2],  u2 = g_edge[j+4],  u3 = g_edge[j+6];
        unsigned int u4 = g_edge[j+8],  u5 = g_edge[j+10], u6 = g_edge[j+12], u7 = g_edge[j+14];
        int s0 = dsrc(u0), s1 = dsrc(u1), s2 = dsrc(u2), s3 = dsrc(u3);
        int s4 = dsrc(u4), s5 = dsrc(u5), s6 = dsrc(u6), s7 = dsrc(u7);
        if (act) {
            uint2 q0 = __ldg(&F[s0*16 + c]);
            uint2 q1 = __ldg(&F[s1*16 + c]);
            uint2 q2 = __ldg(&F[s2*16 + c]);
            uint2 q3 = __ldg(&F[s3*16 + c]);
            uint2 q4 = __ldg(&F[s4*16 + c]);
            uint2 q5 = __ldg(&F[s5*16 + c]);
            uint2 q6 = __ldg(&F[s6*16 + c]);
            uint2 q7 = __ldg(&F[s7*16 + c]);
            float m0 = dnorm(u0), m1 = dnorm(u1), m2 = dnorm(u2), m3 = dnorm(u3);
            float m4 = dnorm(u4), m5 = dnorm(u5), m6 = dnorm(u6), m7 = dnorm(u7);
            ACCUM(q0, m0); ACCUM(q1, m1); ACCUM(q2, m2); ACCUM(q3, m3);
            ACCUM(q4, m4); ACCUM(q5, m5); ACCUM(q6, m6); ACCUM(q7, m7);
        }
        j += 16;
    }
    while (j < e_end) {
        unsigned int u0 = g_edge[j];
        int s0 = dsrc(u0);
        if (act) {
            uint2 q0 = __ldg(&F[s0*16 + c]);
            float m0 = dnorm(u0);
            ACCUM(q0, m0);
        }
        j += 2;
    }
    #undef ACCUM

    // combine the two halves (lanes c and 16+c now hold identical sums)
    acc.x += __shfl_xor_sync(0xffffffffu, acc.x, 16);
    acc.y += __shfl_xor_sync(0xffffffffu, acc.y, 16);
    acc.z += __shfl_xor_sync(0xffffffffu, acc.z, 16);
    acc.w += __shfl_xor_sync(0xffffffffu, acc.w, 16);

    int kk = c % 3, cidx = c / 3;   // chunk c = cidx*3 + kk
    bool act0 = (h == 0) && act;
    if (act0) {
        float* e = ex[warp] + kk*16 + cidx*4;
        e[0] = acc.x; e[1] = acc.y; e[2] = acc.z; e[3] = acc.w;
    }
    __syncwarp();

    // y = af * W[k] + x*root_w + bias, relu — split over 24 lanes (2 outputs each)
    float y0 = 0.f, y1 = 0.f;
    int oo = cidx*4 + h*2;
    if (act) {
        const float* af = ex[warp] + kk*16;
        const float* wk = wsh + kk*256;
        float xv = __ldg(&x[n]);
        #pragma unroll
        for (int f = 0; f < 16; f++) {
            float a = af[f];
            y0 += a * wk[f*16 + oo];
            y1 += a * wk[f*16 + oo + 1];
        }
        y0 = fmaxf(y0 + xv*rwsh[kk*16+oo]   + bsh[kk*16+oo],   0.f);
        y1 = fmaxf(y1 + xv*rwsh[kk*16+oo+1] + bsh[kk*16+oo+1], 0.f);
    }
    __syncwarp();

    if (!finalMode) {
        if (act) {
            __half2 hv2 = __floats2half2_rn(y0, y1);
            ((unsigned int*)D)[n*32 + c*2 + h] = *(unsigned int*)&hv2;
        }
        return;
    }

    // ---- final iteration: mean over stacks + BN + relu + conv2 Horner prep ----
    if (act) {
        ex[warp][kk*16 + oo + 0] = y0;
        ex[warp][kk*16 + oo + 1] = y1;
    }
    __syncwarp();
    if (lane < 16) {
        float m = (ex[warp][lane] + ex[warp][16+lane] + ex[warp][32+lane]) * (1.f/3.f);
        float sc = __ldg(&bng[lane]) * rsqrtf(__ldg(&bnv[lane]) + 1e-5f);
        ex[warp][lane] = fmaxf((m - __ldg(&bnm[lane]))*sc + __ldg(&bnb[lane]), 0.f);
    }
    __syncwarp();
    if (lane == 0) {
        float hv[16];
        #pragma unroll
        for (int f = 0; f < 16; f++) hv[f] = ex[warp][f];
        float o[3] = {0,0,0}, r[3] = {0,0,0};
        #pragma unroll
        for (int k2 = 0; k2 < 3; k2++) {
            #pragma unroll
            for (int f = 0; f < 16; f++) {
                o[k2] += hv[f] * __ldg(&iw2[k2*16+f]);
                r[k2] += hv[f] * __ldg(&rw2[k2*16+f]);
            }
            r[k2] += __ldg(&b2[k2]);
        }
        float z = 0.f, s3v = 0.f, s2v = 0.f, s1v = 0.f, s0v = 0.f;
        #pragma unroll
        for (int k2 = 0; k2 < 3; k2++) {
            float wv = __ldg(&w2[k2]);
            float w2p = wv*wv, w3p = w2p*wv;
            z   += w3p * o[k2];
            s3v += w3p * r[k2];
            s2v += w2p * r[k2];
            s1v += wv  * r[k2];
            s0v += r[k2];
        }
        g_ca[n] = z;
        float4 sv; sv.x = s3v; sv.y = s2v; sv.z = s1v; sv.w = s0v;
        g_s[n] = sv;
    }
}

// ---------------- conv2: 4 scalar Horner SpMV passes ----------------
// result = sigmoid( (A(A(A(A z + s3) + s2) + s1) + s0) / 3 )
// Half-warp per node: 2 nodes/warp, unroll-2 edge loop, 4-level shuffle reduce.
__global__ void __launch_bounds__(256)
k_sp(int pass, float* __restrict__ finalOut) {
    int n = (blockIdx.x*256 + threadIdx.x) >> 4;   // grid exact: 6250*16 = 100000
    int lane = threadIdx.x & 15;
    int st = g_off[n], cn = g_cnt[n];
    int e_end = st + cn;
    const float* src = (pass & 1) ? g_cb : g_ca;
    float s = 0.f;
    int j = st + lane;
    for (; j + 16 < e_end; j += 32) {
        unsigned int u0 = g_edge[j];
        unsigned int u1 = g_edge[j+16];
        s += dnorm(u0) * __ldg(&src[dsrc(u0)]);
        s += dnorm(u1) * __ldg(&src[dsrc(u1)]);
    }
    if (j < e_end) {
        unsigned int u0 = g_edge[j];
        s += dnorm(u0) * __ldg(&src[dsrc(u0)]);
    }
    #pragma unroll
    for (int off = 8; off; off >>= 1) s += __shfl_xor_sync(0xffffffffu, s, off);
    if (lane == 0) {
        float4 sv = __ldg(&g_s[n]);
        float si = (pass == 0) ? sv.x : (pass == 1) ? sv.y : (pass == 2) ? sv.z : sv.w;
        float cval = s + si;
        if (pass == 3) {
            finalOut[n] = 1.f / (1.f + expf(-cval * (1.f/3.f)));
        } else {
            float* dst = (pass & 1) ? g_ca : g_cb;
            dst[n] = cval;
        }
    }
}

// ---------------- driver ----------------
extern "C" void kernel_launch(void* const* d_in, const int* in_sizes, int n_in,
                              void* d_out, int out_size) {
    const float* x    = (const float*)d_in[0];
    const int*   ei   = (const int*)  d_in[1];
    const float* ew   = (const float*)d_in[2];
    const float* c1iw = (const float*)d_in[3];
    const float* c1w  = (const float*)d_in[4];
    const float* c1rw = (const float*)d_in[5];
    const float* c1b  = (const float*)d_in[6];
    const float* bng  = (const float*)d_in[7];
    const float* bnb  = (const float*)d_in[8];
    const float* bnm  = (const float*)d_in[9];
    const float* bnv  = (const float*)d_in[10];
    const float* c2iw = (const float*)d_in[11];
    const float* c2w  = (const float*)d_in[12];
    const float* c2rw = (const float*)d_in[13];
    const float* c2b  = (const float*)d_in[14];
    float* out = (float*)d_out;

    const int* row = ei;
    const int* col = ei + EE;

    const int EG = (EE + 255) / 256;
    const int WG = 12500;   // warp-per-node: 12500 blocks x 8 warps = 100000
    const int HG = 6250;    // half-warp-per-node: 6250 blocks x 16 halves = 100000

    // zero packed deg/cnt + lookback aggregates in one memset node
    void* zp = nullptr;
    cudaGetSymbolAddress(&zp, gz);
    cudaMemsetAsync(zp, 0, sizeof(ZBlock), 0);

    // gcn_norm + CSR build
    k_deg<<<EG, 256>>>(col, ew);
    k_scan<<<NBLK, 1024>>>();
    k_scatter<<<EG, 256>>>(row, col, ew);

    // conv1: rank-1 first propagation (+fused feature init), then 3 SpMM iters
    k_ax<<<WG, 256>>>(x, c1iw, c1rw, c1b);
    k_iter1<<<WG, 256>>>(0, 0, x, c1w, c1rw, c1b, bng, bnb, bnm, bnv, c2iw, c2w, c2rw, c2b); // fa -> fb
    k_iter1<<<WG, 256>>>(1, 0, x, c1w, c1rw, c1b, bng, bnb, bnm, bnv, c2iw, c2w, c2rw, c2b); // fb -> fa
    k_iter1<<<WG, 256>>>(0, 1, x, c1w, c1rw, c1b, bng, bnb, bnm, bnv, c2iw, c2w, c2rw, c2b); // fa -> Horner prep

    // conv2: 4 scalar Horner passes, last fuses sigmoid -> out
    k_sp<<<HG, 256>>>(0, nullptr);  // ca -> cb  (+s3)
    k_sp<<<HG, 256>>>(1, nullptr);  // cb -> ca  (+s2)
    k_sp<<<HG, 256>>>(2, nullptr);  // ca -> cb  (+s1)
    k_sp<<<HG, 256>>>(3, out);      // cb -> sigmoid((c+s0)/3) -> out
}

// round 14
// speedup vs baseline: 1.1549x; 1.0223x over previous
#include <cuda_runtime.h>
#include <cuda_fp16.h>
#include <math.h>

#define NN 100000
#define EE 3200000
#define NBLK 98   // ceil(NN/1024)

// ---------------- scratch (device globals; no runtime allocation) ----------------
// zeroed each run by one cudaMemsetAsync (memset node in the graph)
struct ZBlock {
    unsigned long long pk[NN];  // {count:24bits | fixed-point weight sum:40bits}
    unsigned int agg[NBLK];     // decoupled-lookback aggregates (bit31 = ready)
};
__device__ ZBlock gz;

__device__ float g_dis[NN];
__device__ float g_xs[NN];                    // dis[n] * x[n]  (prescaled gather source)
__device__ int   g_cnt[NN];
__device__ int   g_off[NN];
__device__ int   g_cur[NN];
__device__ unsigned int g_edge[EE];           // packed {ew:fp16-sans-sign [31:17] | src:17 [16:0]}
__device__ __align__(16) uint2 g_fa[NN*16];   // conv1 fp16 feats ping, PREMULTIPLIED by dis[n]
__device__ __align__(16) uint2 g_fb[NN*16];   // conv1 fp16 feats pong, PREMULTIPLIED by dis[n]
__device__ float g_ca[NN];                    // conv2 Horner scalar (dis-prescaled), ping
__device__ float g_cb[NN];                    // conv2 Horner scalar (dis-prescaled), pong
__device__ __align__(16) float4 g_s[NN];      // (s3, s2, s1, s0) per node

__device__ __forceinline__ float dnorm(unsigned int u) {
    return __half2float(__ushort_as_half((unsigned short)(u >> 17)));
}
__device__ __forceinline__ int dsrc(unsigned int u) { return (int)(u & 0x1ffffu); }

// ---------------- gcn_norm + CSR build ----------------
// ONE packed 64-bit fire-and-forget atomic per edge: high 24 bits count,
// low 40 bits fixed-point (2^-28) sum of edge weights.
__global__ void k_deg(const int* __restrict__ col, const float* __restrict__ ew) {
    int e = blockIdx.x*blockDim.x + threadIdx.x;
    if (e < EE) {
        unsigned long long inc = (1ull << 40) |
            (unsigned long long)(ew[e] * 268435456.f + 0.5f);
        atomicAdd(&gz.pk[col[e]], inc);
    }
}

// fused: unpack deg/cnt + dis + xs=dis*x + block scan + lookback + offsets
__global__ void __launch_bounds__(1024) k_scan(const float* __restrict__ x) {
    __shared__ int s[1024];
    __shared__ int sprefix;
    int tid = threadIdx.x, bid = blockIdx.x;
    int i = bid*1024 + tid;
    int v = 0;
    if (i < NN) {
        unsigned long long p = gz.pk[i];
        v = (int)(p >> 40);
        float d = (float)(p & 0xFFFFFFFFFFull) * 3.7252902984619141e-09f; // 2^-28
        float dis = d > 0.f ? rsqrtf(fmaxf(d, 1e-12f)) : 0.f;
        g_dis[i] = dis;
        g_xs[i] = dis * __ldg(&x[i]);
        g_cnt[i] = v;
    }
    s[tid] = v;
    __syncthreads();
    for (int off = 1; off < 1024; off <<= 1) {
        int t = (tid >= off) ? s[tid - off] : 0;
        __syncthreads();
        s[tid] += t;
        __syncthreads();
    }
    int incl = s[tid];
    if (tid == 0) {
        unsigned int aggregate = (unsigned int)s[1023];
        atomicExch(&gz.agg[bid], aggregate | 0x80000000u);
    }
    if (tid < 32) {
        unsigned int sum = 0;
        for (int b = tid; b < bid; b += 32) {
            unsigned int a;
            do { a = *(volatile unsigned int*)&gz.agg[b]; } while (!(a & 0x80000000u));
            sum += a & 0x7fffffffu;
        }
        #pragma unroll
        for (int off = 16; off; off >>= 1) sum += __shfl_xor_sync(0xffffffffu, sum, off);
        if (tid == 0) sprefix = (int)sum;
    }
    __syncthreads();
    if (i < NN) {
        int o = sprefix + incl - v;   // exclusive global offset
        g_off[i] = o;
        g_cur[i] = o;
    }
}

// scatter: NO gathers — the dis factors are separable (dis[row] folded into
// the prescaled gather sources, dis[col] applied per-node post-reduction),
// so the edge record carries only fp16(ew) + src.
__global__ void k_scatter(const int* __restrict__ row, const int* __restrict__ colv,
                          const float* __restrict__ ew) {
    int e = blockIdx.x*blockDim.x + threadIdx.x;
    if (e < EE) {
        int r = row[e], c = colv[e];
        int p = atomicAdd(&g_cur[c], 1);
        unsigned short hb = __half_as_ushort(__float2half_rn(ew[e]));  // ew >= 0
        g_edge[p] = ((unsigned int)hb << 17) | (unsigned int)r;
    }
}

// ---------------- conv1 ----------------
// feat layout per node: 16 uint2 chunks (12 used, 128B record, 128B-aligned);
// chunk ch = cidx*3 + k holds fp16 features [4*cidx .. 4*cidx+3] of stack k,
// PREMULTIPLIED by dis[n] so gathers need no per-edge dis factor.
__device__ __forceinline__ uint2 pack4h(float a, float b, float c, float d) {
    __half2 lo = __floats2half2_rn(a, b);
    __half2 hi = __floats2half2_rn(c, d);
    uint2 o;
    o.x = *(unsigned int*)&lo;
    o.y = *(unsigned int*)&hi;
    return o;
}

// Warp per node: lanes stride over edges (unroll-2), shuffle-reduce,
// Ax = dis[n]*sum; lanes 0..11 write the dis-prescaled fp16 feature state.
__global__ void __launch_bounds__(256)
k_ax(const float* __restrict__ x, const float* __restrict__ iw,
     const float* __restrict__ rw, const float* __restrict__ bs) {
    int n = (blockIdx.x*256 + threadIdx.x) >> 5;   // grid exact: 12500*8 = 100000
    int lane = threadIdx.x & 31;
    int st = g_off[n], cn = g_cnt[n];
    int e_end = st + cn;
    float s = 0.f;
    int j = st + lane;
    for (; j + 32 < e_end; j += 64) {
        unsigned int u0 = g_edge[j];
        unsigned int u1 = g_edge[j+32];
        s += dnorm(u0) * __ldg(&g_xs[dsrc(u0)]);
        s += dnorm(u1) * __ldg(&g_xs[dsrc(u1)]);
    }
    if (j < e_end) {
        unsigned int u0 = g_edge[j];
        s += dnorm(u0) * __ldg(&g_xs[dsrc(u0)]);
    }
    #pragma unroll
    for (int off = 16; off; off >>= 1) s += __shfl_xor_sync(0xffffffffu, s, off);
    float disn = g_dis[n];
    s *= disn;                       // Ax[n]
    float xv = __ldg(&x[n]);
    if (lane < 12) {
        int k = lane % 3, cidx = lane / 3;
        int f = k*16 + cidx*4;
        float f0 = fmaxf(s*__ldg(&iw[f+0]) + xv*__ldg(&rw[f+0]) + __ldg(&bs[f+0]), 0.f);
        float f1 = fmaxf(s*__ldg(&iw[f+1]) + xv*__ldg(&rw[f+1]) + __ldg(&bs[f+1]), 0.f);
        float f2 = fmaxf(s*__ldg(&iw[f+2]) + xv*__ldg(&rw[f+2]) + __ldg(&bs[f+2]), 0.f);
        float f3 = fmaxf(s*__ldg(&iw[f+3]) + xv*__ldg(&rw[f+3]) + __ldg(&bs[f+3]), 0.f);
        g_fa[n*16 + cidx*3 + k] = pack4h(disn*f0, disn*f1, disn*f2, disn*f3);
    }
}

// Warp per node, dual-edge halves, unroll-8 pipelined fp16 gather.
// acc = sum ew * (dis*out)_src; true A(out) = dis[n]*acc (applied pre-matmul).
// Epilogue: fused 16x16 W matmul over 24 lanes + root + relu; normal mode
// stores dis[n]*y; finalMode fuses mean/BN/relu + conv2 Horner prep.
__global__ void __launch_bounds__(256)
k_iter1(int srcIsB, int finalMode,
        const float* __restrict__ x, const float* __restrict__ w,
        const float* __restrict__ rw, const float* __restrict__ bs,
        const float* __restrict__ bng, const float* __restrict__ bnb,
        const float* __restrict__ bnm, const float* __restrict__ bnv,
        const float* __restrict__ iw2, const float* __restrict__ w2,
        const float* __restrict__ rw2, const float* __restrict__ b2) {
    __shared__ float wsh[768];
    __shared__ float rwsh[48], bsh[48];
    __shared__ float ex[8][56];
    for (int i = threadIdx.x; i < 768; i += 256) wsh[i] = w[i];
    if (threadIdx.x < 48) { rwsh[threadIdx.x] = rw[threadIdx.x]; bsh[threadIdx.x] = bs[threadIdx.x]; }
    __syncthreads();

    int warp = threadIdx.x >> 5;
    int lane = threadIdx.x & 31;
    int h = lane >> 4, c = lane & 15;
    bool act = c < 12;
    int n = blockIdx.x*8 + warp;                 // grid exact
    int st = g_off[n], cn = g_cnt[n];
    int e_end = st + cn;
    const uint2* F = srcIsB ? g_fb : g_fa;
    uint2*       D = srcIsB ? g_fa : g_fb;

    float4 acc = make_float4(0.f, 0.f, 0.f, 0.f);
    int j = st + h;

    #define ACCUM(q, m) { \
        float2 _a = __half22float2(*(const __half2*)&(q).x); \
        float2 _b = __half22float2(*(const __half2*)&(q).y); \
        acc.x += (m)*_a.x; acc.y += (m)*_a.y; acc.z += (m)*_b.x; acc.w += (m)*_b.y; }

    while (j + 14 < e_end) {
        unsigned int u0 = g_edge[j],    u1 = g_edge[j+2],  u2 = g_edge[j+4],  u3 = g_edge[j+6];
        unsigned int u4 = g_edge[j+8],  u5 = g_edge[j+10], u6 = g_edge[j+12], u7 = g_edge[j+14];
        int s0 = dsrc(u0), s1 = dsrc(u1), s2 = dsrc(u2), s3 = dsrc(u3);
        int s4 = dsrc(u4), s5 = dsrc(u5), s6 = dsrc(u6), s7 = dsrc(u7);
        if (act) {
            uint2 q0 = __ldg(&F[s0*16 + c]);
            uint2 q1 = __ldg(&F[s1*16 + c]);
            uint2 q2 = __ldg(&F[s2*16 + c]);
            uint2 q3 = __ldg(&F[s3*16 + c]);
            uint2 q4 = __ldg(&F[s4*16 + c]);
            uint2 q5 = __ldg(&F[s5*16 + c]);
            uint2 q6 = __ldg(&F[s6*16 + c]);
            uint2 q7 = __ldg(&F[s7*16 + c]);
            float m0 = dnorm(u0), m1 = dnorm(u1), m2 = dnorm(u2), m3 = dnorm(u3);
            float m4 = dnorm(u4), m5 = dnorm(u5), m6 = dnorm(u6), m7 = dnorm(u7);
            ACCUM(q0, m0); ACCUM(q1, m1); ACCUM(q2, m2); ACCUM(q3, m3);
            ACCUM(q4, m4); ACCUM(q5, m5); ACCUM(q6, m6); ACCUM(q7, m7);
        }
        j += 16;
    }
    while (j < e_end) {
        unsigned int u0 = g_edge[j];
        int s0 = dsrc(u0);
        if (act) {
            uint2 q0 = __ldg(&F[s0*16 + c]);
            float m0 = dnorm(u0);
            ACCUM(q0, m0);
        }
        j += 2;
    }
    #undef ACCUM

    // combine the two halves, apply dis[n] (the dst-side normalization factor)
    float disn = g_dis[n];
    acc.x += __shfl_xor_sync(0xffffffffu, acc.x, 16);
    acc.y += __shfl_xor_sync(0xffffffffu, acc.y, 16);
    acc.z += __shfl_xor_sync(0xffffffffu, acc.z, 16);
    acc.w += __shfl_xor_sync(0xffffffffu, acc.w, 16);
    acc.x *= disn; acc.y *= disn; acc.z *= disn; acc.w *= disn;

    int kk = c % 3, cidx = c / 3;   // chunk c = cidx*3 + kk
    bool act0 = (h == 0) && act;
    if (act0) {
        float* e = ex[warp] + kk*16 + cidx*4;
        e[0] = acc.x; e[1] = acc.y; e[2] = acc.z; e[3] = acc.w;
    }
    __syncwarp();

    // y = af * W[k] + x*root_w + bias, relu — split over 24 lanes (2 outputs each)
    float y0 = 0.f, y1 = 0.f;
    int oo = cidx*4 + h*2;
    if (act) {
        const float* af = ex[warp] + kk*16;
        const float* wk = wsh + kk*256;
        float xv = __ldg(&x[n]);
        #pragma unroll
        for (int f = 0; f < 16; f++) {
            float a = af[f];
            y0 += a * wk[f*16 + oo];
            y1 += a * wk[f*16 + oo + 1];
        }
        y0 = fmaxf(y0 + xv*rwsh[kk*16+oo]   + bsh[kk*16+oo],   0.f);
        y1 = fmaxf(y1 + xv*rwsh[kk*16+oo+1] + bsh[kk*16+oo+1], 0.f);
    }
    __syncwarp();

    if (!finalMode) {
        if (act) {
            __half2 hv2 = __floats2half2_rn(disn*y0, disn*y1);   // prescale for next gather
            ((unsigned int*)D)[n*32 + c*2 + h] = *(unsigned int*)&hv2;
        }
        return;
    }

    // ---- final iteration: mean over stacks + BN + relu + conv2 Horner prep ----
    if (act) {
        ex[warp][kk*16 + oo + 0] = y0;
        ex[warp][kk*16 + oo + 1] = y1;
    }
    __syncwarp();
    if (lane < 16) {
        float m = (ex[warp][lane] + ex[warp][16+lane] + ex[warp][32+lane]) * (1.f/3.f);
        float sc = __ldg(&bng[lane]) * rsqrtf(__ldg(&bnv[lane]) + 1e-5f);
        ex[warp][lane] = fmaxf((m - __ldg(&bnm[lane]))*sc + __ldg(&bnb[lane]), 0.f);
    }
    __syncwarp();
    if (lane == 0) {
        float hv[16];
        #pragma unroll
        for (int f = 0; f < 16; f++) hv[f] = ex[warp][f];
        float o[3] = {0,0,0}, r[3] = {0,0,0};
        #pragma unroll
        for (int k2 = 0; k2 < 3; k2++) {
            #pragma unroll
            for (int f = 0; f < 16; f++) {
                o[k2] += hv[f] * __ldg(&iw2[k2*16+f]);
                r[k2] += hv[f] * __ldg(&rw2[k2*16+f]);
            }
            r[k2] += __ldg(&b2[k2]);
        }
        float z = 0.f, s3v = 0.f, s2v = 0.f, s1v = 0.f, s0v = 0.f;
        #pragma unroll
        for (int k2 = 0; k2 < 3; k2++) {
            float wv = __ldg(&w2[k2]);
            float w2p = wv*wv, w3p = w2p*wv;
            z   += w3p * o[k2];
            s3v += w3p * r[k2];
            s2v += w2p * r[k2];
            s1v += wv  * r[k2];
            s0v += r[k2];
        }
        g_ca[n] = z * disn;   // prescaled for the first k_sp gather
        float4 sv; sv.x = s3v; sv.y = s2v; sv.z = s1v; sv.w = s0v;
        g_s[n] = sv;
    }
}

// ---------------- conv2: 4 scalar Horner SpMV passes ----------------
// state arrays hold dis[n]*c; cval = dis[n]*sum(ew*state_src) + s_i.
// result = sigmoid( cval_final / 3 ).  Half-warp per node, unroll-2.
__global__ void __launch_bounds__(256)
k_sp(int pass, float* __restrict__ finalOut) {
    int n = (blockIdx.x*256 + threadIdx.x) >> 4;   // grid exact: 6250*16 = 100000
    int lane = threadIdx.x & 15;
    int st = g_off[n], cn = g_cnt[n];
    int e_end = st + cn;
    const float* src = (pass & 1) ? g_cb : g_ca;
    float s = 0.f;
    int j = st + lane;
    for (; j + 16 < e_end; j += 32) {
        unsigned int u0 = g_edge[j];
        unsigned int u1 = g_edge[j+16];
        s += dnorm(u0) * __ldg(&src[dsrc(u0)]);
        s += dnorm(u1) * __ldg(&src[dsrc(u1)]);
    }
    if (j < e_end) {
        unsigned int u0 = g_edge[j];
        s += dnorm(u0) * __ldg(&src[dsrc(u0)]);
    }
    #pragma unroll
    for (int off = 8; off; off >>= 1) s += __shfl_xor_sync(0xffffffffu, s, off);
    if (lane == 0) {
        float disn = g_dis[n];
        float4 sv = __ldg(&g_s[n]);
        float si = (pass == 0) ? sv.x : (pass == 1) ? sv.y : (pass == 2) ? sv.z : sv.w;
        float cval = disn*s + si;
        if (pass == 3) {
            finalOut[n] = 1.f / (1.f + expf(-cval * (1.f/3.f)));
        } else {
            float* dst = (pass & 1) ? g_ca : g_cb;
            dst[n] = cval * disn;    // prescale for next gather
        }
    }
}

// ---------------- driver ----------------
extern "C" void kernel_launch(void* const* d_in, const int* in_sizes, int n_in,
                              void* d_out, int out_size) {
    const float* x    = (const float*)d_in[0];
    const int*   ei   = (const int*)  d_in[1];
    const float* ew   = (const float*)d_in[2];
    const float* c1iw = (const float*)d_in[3];
    const float* c1w  = (const float*)d_in[4];
    const float* c1rw = (const float*)d_in[5];
    const float* c1b  = (const float*)d_in[6];
    const float* bng  = (const float*)d_in[7];
    const float* bnb  = (const float*)d_in[8];
    const float* bnm  = (const float*)d_in[9];
    const float* bnv  = (const float*)d_in[10];
    const float* c2iw = (const float*)d_in[11];
    const float* c2w  = (const float*)d_in[12];
    const float* c2rw = (const float*)d_in[13];
    const float* c2b  = (const float*)d_in[14];
    float* out = (float*)d_out;

    const int* row = ei;
    const int* col = ei + EE;

    const int EG = (EE + 255) / 256;
    const int WG = 12500;   // warp-per-node: 12500 blocks x 8 warps = 100000
    const int HG = 6250;    // half-warp-per-node: 6250 blocks x 16 halves = 100000

    // zero packed deg/cnt + lookback aggregates in one memset node
    void* zp = nullptr;
    cudaGetSymbolAddress(&zp, gz);
    cudaMemsetAsync(zp, 0, sizeof(ZBlock), 0);

    // gcn_norm + CSR build (scatter is gather-free; dis factors separable)
    k_deg<<<EG, 256>>>(col, ew);
    k_scan<<<NBLK, 1024>>>(x);
    k_scatter<<<EG, 256>>>(row, col, ew);

    // conv1: rank-1 first propagation (+fused feature init), then 3 SpMM iters
    k_ax<<<WG, 256>>>(x, c1iw, c1rw, c1b);
    k_iter1<<<WG, 256>>>(0, 0, x, c1w, c1rw, c1b, bng, bnb, bnm, bnv, c2iw, c2w, c2rw, c2b); // fa -> fb
    k_iter1<<<WG, 256>>>(1, 0, x, c1w, c1rw, c1b, bng, bnb, bnm, bnv, c2iw, c2w, c2rw, c2b); // fb -> fa
    k_iter1<<<WG, 256>>>(0, 1, x, c1w, c1rw, c1b, bng, bnb, bnm, bnv, c2iw, c2w, c2rw, c2b); // fa -> Horner prep

    // conv2: 4 scalar Horner passes, last fuses sigmoid -> out
    k_sp<<<HG, 256>>>(0, nullptr);  // ca -> cb  (+s3)
    k_sp<<<HG, 256>>>(1, nullptr);  // cb -> ca  (+s2)
    k_sp<<<HG, 256>>>(2, nullptr);  // ca -> cb  (+s1)
    k_sp<<<HG, 256>>>(3, out);      // cb -> sigmoid((c+s0)/3) -> out
}

// round 15
// speedup vs baseline: 1.1720x; 1.0148x over previous
#include <cuda_runtime.h>
#include <cuda_fp16.h>
#include <math.h>

#define NN 100000
#define EE 3200000
#define NBLK 98   // ceil(NN/1024)

// ---------------- scratch (device globals; no runtime allocation) ----------------
struct ZBlock {
    unsigned long long pk[NN];  // {count:24bits | fixed-point weight sum:40bits}
    unsigned int agg[NBLK];     // decoupled-lookback aggregates (bit31 = ready)
};
__device__ ZBlock gz;

__device__ float g_dis[NN];
__device__ float g_xs[NN];                    // dis[n] * x[n]  (prescaled gather source)
__device__ int   g_cnt[NN];
__device__ int   g_off[NN];
__device__ int   g_cur[NN];
__device__ unsigned int g_edge[EE];           // packed {ew:fp16-sans-sign [31:17] | src:17 [16:0]}
__device__ __align__(16) uint2 g_fa[NN*16];   // conv1 fp16 feats ping, PREMULTIPLIED by dis[n]
__device__ __align__(16) uint2 g_fb[NN*16];   // conv1 fp16 feats pong
__device__ float g_ca[NN];                    // conv2 Horner scalar (dis-prescaled), ping
__device__ float g_cb[NN];                    // conv2 Horner scalar (dis-prescaled), pong
__device__ __align__(16) float4 g_s[NN];      // (s3, s2, s1, s0) per node

__device__ __forceinline__ float dnorm(unsigned int u) {
    return __half2float(__ushort_as_half((unsigned short)(u >> 17)));
}
__device__ __forceinline__ int dsrc(unsigned int u) { return (int)(u & 0x1ffffu); }

// ---------------- gcn_norm + CSR build ----------------
__global__ void k_deg(const int* __restrict__ col, const float* __restrict__ ew) {
    int e = blockIdx.x*blockDim.x + threadIdx.x;
    if (e < EE) {
        unsigned long long inc = (1ull << 40) |
            (unsigned long long)(ew[e] * 268435456.f + 0.5f);
        atomicAdd(&gz.pk[col[e]], inc);
    }
}

__global__ void __launch_bounds__(1024) k_scan(const float* __restrict__ x) {
    __shared__ int s[1024];
    __shared__ int sprefix;
    int tid = threadIdx.x, bid = blockIdx.x;
    int i = bid*1024 + tid;
    int v = 0;
    if (i < NN) {
        unsigned long long p = gz.pk[i];
        v = (int)(p >> 40);
        float d = (float)(p & 0xFFFFFFFFFFull) * 3.7252902984619141e-09f; // 2^-28
        float dis = d > 0.f ? rsqrtf(fmaxf(d, 1e-12f)) : 0.f;
        g_dis[i] = dis;
        g_xs[i] = dis * __ldg(&x[i]);
        g_cnt[i] = v;
    }
    s[tid] = v;
    __syncthreads();
    for (int off = 1; off < 1024; off <<= 1) {
        int t = (tid >= off) ? s[tid - off] : 0;
        __syncthreads();
        s[tid] += t;
        __syncthreads();
    }
    int incl = s[tid];
    if (tid == 0) {
        unsigned int aggregate = (unsigned int)s[1023];
        atomicExch(&gz.agg[bid], aggregate | 0x80000000u);
    }
    if (tid < 32) {
        unsigned int sum = 0;
        for (int b = tid; b < bid; b += 32) {
            unsigned int a;
            do { a = *(volatile unsigned int*)&gz.agg[b]; } while (!(a & 0x80000000u));
            sum += a & 0x7fffffffu;
        }
        #pragma unroll
        for (int off = 16; off; off >>= 1) sum += __shfl_xor_sync(0xffffffffu, sum, off);
        if (tid == 0) sprefix = (int)sum;
    }
    __syncthreads();
    if (i < NN) {
        int o = sprefix + incl - v;
        g_off[i] = o;
        g_cur[i] = o;
    }
}

// gather-free scatter (dis factors separable)
__global__ void k_scatter(const int* __restrict__ row, const int* __restrict__ colv,
                          const float* __restrict__ ew) {
    int e = blockIdx.x*blockDim.x + threadIdx.x;
    if (e < EE) {
        int r = row[e], c = colv[e];
        int p = atomicAdd(&g_cur[c], 1);
        unsigned short hb = __half_as_ushort(__float2half_rn(ew[e]));  // ew >= 0
        g_edge[p] = ((unsigned int)hb << 17) | (unsigned int)r;
    }
}

// ---------------- conv1 ----------------
__device__ __forceinline__ uint2 pack4h(float a, float b, float c, float d) {
    __half2 lo = __floats2half2_rn(a, b);
    __half2 hi = __floats2half2_rn(c, d);
    uint2 o;
    o.x = *(unsigned int*)&lo;
    o.y = *(unsigned int*)&hi;
    return o;
}

// Half-warp per node (k_sp structure): 16 lanes stride edges (unroll-2),
// 4-level reduce, then lanes 0..11 of each half write dis-prescaled feat0.
__global__ void __launch_bounds__(256)
k_ax(const float* __restrict__ x, const float* __restrict__ iw,
     const float* __restrict__ rw, const float* __restrict__ bs) {
    int n = (blockIdx.x*256 + threadIdx.x) >> 4;   // grid exact: 6250*16 = 100000
    int lane = threadIdx.x & 15;
    int st = g_off[n], cn = g_cnt[n];
    int e_end = st + cn;
    float s = 0.f;
    int j = st + lane;
    for (; j + 16 < e_end; j += 32) {
        unsigned int u0 = g_edge[j];
        unsigned int u1 = g_edge[j+16];
        s += dnorm(u0) * __ldg(&g_xs[dsrc(u0)]);
        s += dnorm(u1) * __ldg(&g_xs[dsrc(u1)]);
    }
    if (j < e_end) {
        unsigned int u0 = g_edge[j];
        s += dnorm(u0) * __ldg(&g_xs[dsrc(u0)]);
    }
    #pragma unroll
    for (int off = 8; off; off >>= 1) s += __shfl_xor_sync(0xffffffffu, s, off);
    float disn = g_dis[n];
    s *= disn;                       // Ax[n]
    float xv = __ldg(&x[n]);
    if (lane < 12) {
        int k = lane % 3, cidx = lane / 3;
        int f = k*16 + cidx*4;
        float f0 = fmaxf(s*__ldg(&iw[f+0]) + xv*__ldg(&rw[f+0]) + __ldg(&bs[f+0]), 0.f);
        float f1 = fmaxf(s*__ldg(&iw[f+1]) + xv*__ldg(&rw[f+1]) + __ldg(&bs[f+1]), 0.f);
        float f2 = fmaxf(s*__ldg(&iw[f+2]) + xv*__ldg(&rw[f+2]) + __ldg(&bs[f+2]), 0.f);
        float f3 = fmaxf(s*__ldg(&iw[f+3]) + xv*__ldg(&rw[f+3]) + __ldg(&bs[f+3]), 0.f);
        g_fa[n*16 + cidx*3 + k] = pack4h(disn*f0, disn*f1, disn*f2, disn*f3);
    }
}

// Warp per node, dual-edge halves, GRADUATED unroll (8/4/2/1) pipelined fp16
// gather so the tail never drops to MLP=1 until <2 edges remain.
// acc = sum ew*(dis*out)_src; A(out) = dis[n]*acc. Epilogue: 16x16 W matmul
// over 24 lanes + root + relu; finalMode fuses mean/BN/relu + Horner prep.
__global__ void __launch_bounds__(256)
k_iter1(int srcIsB, int finalMode,
        const float* __restrict__ x, const float* __restrict__ w,
        const float* __restrict__ rw, const float* __restrict__ bs,
        const float* __restrict__ bng, const float* __restrict__ bnb,
        const float* __restrict__ bnm, const float* __restrict__ bnv,
        const float* __restrict__ iw2, const float* __restrict__ w2,
        const float* __restrict__ rw2, const float* __restrict__ b2) {
    __shared__ float wsh[768];
    __shared__ float rwsh[48], bsh[48];
    __shared__ float ex[8][56];
    for (int i = threadIdx.x; i < 768; i += 256) wsh[i] = w[i];
    if (threadIdx.x < 48) { rwsh[threadIdx.x] = rw[threadIdx.x]; bsh[threadIdx.x] = bs[threadIdx.x]; }
    __syncthreads();

    int warp = threadIdx.x >> 5;
    int lane = threadIdx.x & 31;
    int h = lane >> 4, c = lane & 15;
    bool act = c < 12;
    int n = blockIdx.x*8 + warp;                 // grid exact
    int st = g_off[n], cn = g_cnt[n];
    int e_end = st + cn;
    const uint2* F = srcIsB ? g_fb : g_fa;
    uint2*       D = srcIsB ? g_fa : g_fb;

    float4 acc = make_float4(0.f, 0.f, 0.f, 0.f);
    int j = st + h;

    #define ACCUM(q, m) { \
        float2 _a = __half22float2(*(const __half2*)&(q).x); \
        float2 _b = __half22float2(*(const __half2*)&(q).y); \
        acc.x += (m)*_a.x; acc.y += (m)*_a.y; acc.z += (m)*_b.x; acc.w += (m)*_b.y; }

    while (j + 14 < e_end) {        // 8 edges per half
        unsigned int u0 = g_edge[j],    u1 = g_edge[j+2],  u2 = g_edge[j+4],  u3 = g_edge[j+6];
        unsigned int u4 = g_edge[j+8],  u5 = g_edge[j+10], u6 = g_edge[j+12], u7 = g_edge[j+14];
        int s0 = dsrc(u0), s1 = dsrc(u1), s2 = dsrc(u2), s3 = dsrc(u3);
        int s4 = dsrc(u4), s5 = dsrc(u5), s6 = dsrc(u6), s7 = dsrc(u7);
        if (act) {
            uint2 q0 = __ldg(&F[s0*16 + c]);
            uint2 q1 = __ldg(&F[s1*16 + c]);
            uint2 q2 = __ldg(&F[s2*16 + c]);
            uint2 q3 = __ldg(&F[s3*16 + c]);
            uint2 q4 = __ldg(&F[s4*16 + c]);
            uint2 q5 = __ldg(&F[s5*16 + c]);
            uint2 q6 = __ldg(&F[s6*16 + c]);
            uint2 q7 = __ldg(&F[s7*16 + c]);
            float m0 = dnorm(u0), m1 = dnorm(u1), m2 = dnorm(u2), m3 = dnorm(u3);
            float m4 = dnorm(u4), m5 = dnorm(u5), m6 = dnorm(u6), m7 = dnorm(u7);
            ACCUM(q0, m0); ACCUM(q1, m1); ACCUM(q2, m2); ACCUM(q3, m3);
            ACCUM(q4, m4); ACCUM(q5, m5); ACCUM(q6, m6); ACCUM(q7, m7);
        }
        j += 16;
    }
    if (j + 6 < e_end) {            // 4 edges per half
        unsigned int u0 = g_edge[j], u1 = g_edge[j+2], u2 = g_edge[j+4], u3 = g_edge[j+6];
        int s0 = dsrc(u0), s1 = dsrc(u1), s2 = dsrc(u2), s3 = dsrc(u3);
        if (act) {
            uint2 q0 = __ldg(&F[s0*16 + c]);
            uint2 q1 = __ldg(&F[s1*16 + c]);
            uint2 q2 = __ldg(&F[s2*16 + c]);
            uint2 q3 = __ldg(&F[s3*16 + c]);
            float m0 = dnorm(u0), m1 = dnorm(u1), m2 = dnorm(u2), m3 = dnorm(u3);
            ACCUM(q0, m0); ACCUM(q1, m1); ACCUM(q2, m2); ACCUM(q3, m3);
        }
        j += 8;
    }
    if (j + 2 < e_end) {            // 2 edges per half
        unsigned int u0 = g_edge[j], u1 = g_edge[j+2];
        int s0 = dsrc(u0), s1 = dsrc(u1);
        if (act) {
            uint2 q0 = __ldg(&F[s0*16 + c]);
            uint2 q1 = __ldg(&F[s1*16 + c]);
            float m0 = dnorm(u0), m1 = dnorm(u1);
            ACCUM(q0, m0); ACCUM(q1, m1);
        }
        j += 4;
    }
    if (j < e_end) {                // final edge
        unsigned int u0 = g_edge[j];
        int s0 = dsrc(u0);
        if (act) {
            uint2 q0 = __ldg(&F[s0*16 + c]);
            float m0 = dnorm(u0);
            ACCUM(q0, m0);
        }
    }
    #undef ACCUM

    // combine the two halves, apply dis[n]
    float disn = g_dis[n];
    acc.x += __shfl_xor_sync(0xffffffffu, acc.x, 16);
    acc.y += __shfl_xor_sync(0xffffffffu, acc.y, 16);
    acc.z += __shfl_xor_sync(0xffffffffu, acc.z, 16);
    acc.w += __shfl_xor_sync(0xffffffffu, acc.w, 16);
    acc.x *= disn; acc.y *= disn; acc.z *= disn; acc.w *= disn;

    int kk = c % 3, cidx = c / 3;   // chunk c = cidx*3 + kk
    bool act0 = (h == 0) && act;
    if (act0) {
        float* e = ex[warp] + kk*16 + cidx*4;
        e[0] = acc.x; e[1] = acc.y; e[2] = acc.z; e[3] = acc.w;
    }
    __syncwarp();

    // y = af * W[k] + x*root_w + bias, relu — split over 24 lanes
    float y0 = 0.f, y1 = 0.f;
    int oo = cidx*4 + h*2;
    if (act) {
        const float* af = ex[warp] + kk*16;
        const float* wk = wsh + kk*256;
        float xv = __ldg(&x[n]);
        #pragma unroll
        for (int f = 0; f < 16; f++) {
            float a = af[f];
            y0 += a * wk[f*16 + oo];
            y1 += a * wk[f*16 + oo + 1];
        }
        y0 = fmaxf(y0 + xv*rwsh[kk*16+oo]   + bsh[kk*16+oo],   0.f);
        y1 = fmaxf(y1 + xv*rwsh[kk*16+oo+1] + bsh[kk*16+oo+1], 0.f);
    }
    __syncwarp();

    if (!finalMode) {
        if (act) {
            __half2 hv2 = __floats2half2_rn(disn*y0, disn*y1);   // prescale for next gather
            ((unsigned int*)D)[n*32 + c*2 + h] = *(unsigned int*)&hv2;
        }
        return;
    }

    // ---- final iteration: mean over stacks + BN + relu + conv2 Horner prep ----
    if (act) {
        ex[warp][kk*16 + oo + 0] = y0;
        ex[warp][kk*16 + oo + 1] = y1;
    }
    __syncwarp();
    if (lane < 16) {
        float m = (ex[warp][lane] + ex[warp][16+lane] + ex[warp][32+lane]) * (1.f/3.f);
        float sc = __ldg(&bng[lane]) * rsqrtf(__ldg(&bnv[lane]) + 1e-5f);
        ex[warp][lane] = fmaxf((m - __ldg(&bnm[lane]))*sc + __ldg(&bnb[lane]), 0.f);
    }
    __syncwarp();
    if (lane == 0) {
        float hv[16];
        #pragma unroll
        for (int f = 0; f < 16; f++) hv[f] = ex[warp][f];
        float o[3] = {0,0,0}, r[3] = {0,0,0};
        #pragma unroll
        for (int k2 = 0; k2 < 3; k2++) {
            #pragma unroll
            for (int f = 0; f < 16; f++) {
                o[k2] += hv[f] * __ldg(&iw2[k2*16+f]);
                r[k2] += hv[f] * __ldg(&rw2[k2*16+f]);
            }
            r[k2] += __ldg(&b2[k2]);
        }
        float z = 0.f, s3v = 0.f, s2v = 0.f, s1v = 0.f, s0v = 0.f;
        #pragma unroll
        for (int k2 = 0; k2 < 3; k2++) {
            float wv = __ldg(&w2[k2]);
            float w2p = wv*wv, w3p = w2p*wv;
            z   += w3p * o[k2];
            s3v += w3p * r[k2];
            s2v += w2p * r[k2];
            s1v += wv  * r[k2];
            s0v += r[k2];
        }
        g_ca[n] = z * disn;   // prescaled for the first k_sp gather
        float4 sv; sv.x = s3v; sv.y = s2v; sv.z = s1v; sv.w = s0v;
        g_s[n] = sv;
    }
}

// ---------------- conv2: 4 scalar Horner SpMV passes ----------------
__global__ void __launch_bounds__(256)
k_sp(int pass, float* __restrict__ finalOut) {
    int n = (blockIdx.x*256 + threadIdx.x) >> 4;   // grid exact: 6250*16 = 100000
    int lane = threadIdx.x & 15;
    int st = g_off[n], cn = g_cnt[n];
    int e_end = st + cn;
    const float* src = (pass & 1) ? g_cb : g_ca;
    float s = 0.f;
    int j = st + lane;
    for (; j + 16 < e_end; j += 32) {
        unsigned int u0 = g_edge[j];
        unsigned int u1 = g_edge[j+16];
        s += dnorm(u0) * __ldg(&src[dsrc(u0)]);
        s += dnorm(u1) * __ldg(&src[dsrc(u1)]);
    }
    if (j < e_end) {
        unsigned int u0 = g_edge[j];
        s += dnorm(u0) * __ldg(&src[dsrc(u0)]);
    }
    #pragma unroll
    for (int off = 8; off; off >>= 1) s += __shfl_xor_sync(0xffffffffu, s, off);
    if (lane == 0) {
        float disn = g_dis[n];
        float4 sv = __ldg(&g_s[n]);
        float si = (pass == 0) ? sv.x : (pass == 1) ? sv.y : (pass == 2) ? sv.z : sv.w;
        float cval = disn*s + si;
        if (pass == 3) {
            finalOut[n] = 1.f / (1.f + expf(-cval * (1.f/3.f)));
        } else {
            float* dst = (pass & 1) ? g_ca : g_cb;
            dst[n] = cval * disn;    // prescale for next gather
        }
    }
}

// ---------------- driver ----------------
extern "C" void kernel_launch(void* const* d_in, const int* in_sizes, int n_in,
                              void* d_out, int out_size) {
    const float* x    = (const float*)d_in[0];
    const int*   ei   = (const int*)  d_in[1];
    const float* ew   = (const float*)d_in[2];
    const float* c1iw = (const float*)d_in[3];
    const float* c1w  = (const float*)d_in[4];
    const float* c1rw = (const float*)d_in[5];
    const float* c1b  = (const float*)d_in[6];
    const float* bng  = (const float*)d_in[7];
    const float* bnb  = (const float*)d_in[8];
    const float* bnm  = (const float*)d_in[9];
    const float* bnv  = (const float*)d_in[10];
    const float* c2iw = (const float*)d_in[11];
    const float* c2w  = (const float*)d_in[12];
    const float* c2rw = (const float*)d_in[13];
    const float* c2b  = (const float*)d_in[14];
    float* out = (float*)d_out;

    const int* row = ei;
    const int* col = ei + EE;

    const int EG = (EE + 255) / 256;
    const int WG = 12500;   // warp-per-node: 12500 blocks x 8 warps = 100000
    const int HG = 6250;    // half-warp-per-node: 6250 blocks x 16 halves = 100000

    void* zp = nullptr;
    cudaGetSymbolAddress(&zp, gz);
    cudaMemsetAsync(zp, 0, sizeof(ZBlock), 0);

    // gcn_norm + CSR build (scatter is gather-free; dis factors separable)
    k_deg<<<EG, 256>>>(col, ew);
    k_scan<<<NBLK, 1024>>>(x);
    k_scatter<<<EG, 256>>>(row, col, ew);

    // conv1: rank-1 first propagation (+fused feature init), then 3 SpMM iters
    k_ax<<<HG, 256>>>(x, c1iw, c1rw, c1b);
    k_iter1<<<WG, 256>>>(0, 0, x, c1w, c1rw, c1b, bng, bnb, bnm, bnv, c2iw, c2w, c2rw, c2b); // fa -> fb
    k_iter1<<<WG, 256>>>(1, 0, x, c1w, c1rw, c1b, bng, bnb, bnm, bnv, c2iw, c2w, c2rw, c2b); // fb -> fa
    k_iter1<<<WG, 256>>>(0, 1, x, c1w, c1rw, c1b, bng, bnb, bnm, bnv, c2iw, c2w, c2rw, c2b); // fa -> Horner prep

    // conv2: 4 scalar Horner passes, last fuses sigmoid -> out
    k_sp<<<HG, 256>>>(0, nullptr);  // ca -> cb  (+s3)
    k_sp<<<HG, 256>>>(1, nullptr);  // cb -> ca  (+s2)
    k_sp<<<HG, 256>>>(2, nullptr);  // ca -> cb  (+s1)
    k_sp<<<HG, 256>>>(3, out);      // cb -> sigmoid((c+s0)/3) -> out
}

// round 16
// speedup vs baseline: 1.1887x; 1.0142x over previous
#include <cuda_runtime.h>
#include <cuda_fp16.h>
#include <cuda_fp8.h>
#include <math.h>

#define NN 100000
#define EE 3200000
#define NBLK 98   // ceil(NN/1024)

// ---------------- scratch (device globals; no runtime allocation) ----------------
struct ZBlock {
    unsigned long long pk[NN];  // {count:24bits | fixed-point weight sum:40bits}
    unsigned int agg[NBLK];     // decoupled-lookback aggregates (bit31 = ready)
};
__device__ ZBlock gz;

__device__ float g_dis[NN];
__device__ float g_xs[NN];                    // dis[n] * x[n]  (prescaled gather source)
__device__ int   g_cnt[NN];
__device__ int   g_off[NN];
__device__ int   g_cur[NN];
__device__ unsigned int g_edge[EE];           // packed {ew:fp16-sans-sign [31:17] | src:17 [16:0]}
// conv1 feats: fp8 e4m3, PREMULTIPLIED by 16*dis[n]; 48 of 64 bytes used per
// 64B-aligned record -> 12-lane gather spans 2 sectors per edge.
__device__ __align__(128) unsigned int g_fa[NN*16];
__device__ __align__(128) unsigned int g_fb[NN*16];
__device__ float g_ca[NN];                    // conv2 Horner scalar (dis-prescaled), ping
__device__ float g_cb[NN];                    // conv2 Horner scalar (dis-prescaled), pong
__device__ __align__(16) float4 g_s[NN];      // (s3, s2, s1, s0) per node

#define F8SCALE 16.f
#define F8INV   (1.f/16.f)

__device__ __forceinline__ float dnorm(unsigned int u) {
    return __half2float(__ushort_as_half((unsigned short)(u >> 17)));
}
__device__ __forceinline__ int dsrc(unsigned int u) { return (int)(u & 0x1ffffu); }

__device__ __forceinline__ unsigned short pack2f8(float a, float b) {
    return (unsigned short)__nv_cvt_float2_to_fp8x2(make_float2(a, b), __NV_SATFINITE, __NV_E4M3);
}
__device__ __forceinline__ unsigned int pack4f8(float a, float b, float c, float d) {
    return (unsigned int)pack2f8(a, b) | ((unsigned int)pack2f8(c, d) << 16);
}
__device__ __forceinline__ float4 unpack4f8(unsigned int u) {
    __half2_raw l = __nv_cvt_fp8x2_to_halfraw2((__nv_fp8x2_storage_t)(u & 0xffffu), __NV_E4M3);
    __half2_raw h = __nv_cvt_fp8x2_to_halfraw2((__nv_fp8x2_storage_t)(u >> 16), __NV_E4M3);
    float2 lf = __half22float2(*(__half2*)&l);
    float2 hf = __half22float2(*(__half2*)&h);
    return make_float4(lf.x, lf.y, hf.x, hf.y);
}

// ---------------- gcn_norm + CSR build ----------------
__global__ void k_deg(const int* __restrict__ col, const float* __restrict__ ew) {
    int e = blockIdx.x*blockDim.x + threadIdx.x;
    if (e < EE) {
        unsigned long long inc = (1ull << 40) |
            (unsigned long long)(ew[e] * 268435456.f + 0.5f);
        atomicAdd(&gz.pk[col[e]], inc);
    }
}

__global__ void __launch_bounds__(1024) k_scan(const float* __restrict__ x) {
    __shared__ int s[1024];
    __shared__ int sprefix;
    int tid = threadIdx.x, bid = blockIdx.x;
    int i = bid*1024 + tid;
    int v = 0;
    if (i < NN) {
        unsigned long long p = gz.pk[i];
        v = (int)(p >> 40);
        float d = (float)(p & 0xFFFFFFFFFFull) * 3.7252902984619141e-09f; // 2^-28
        float dis = d > 0.f ? rsqrtf(fmaxf(d, 1e-12f)) : 0.f;
        g_dis[i] = dis;
        g_xs[i] = dis * __ldg(&x[i]);
        g_cnt[i] = v;
    }
    s[tid] = v;
    __syncthreads();
    for (int off = 1; off < 1024; off <<= 1) {
        int t = (tid >= off) ? s[tid - off] : 0;
        __syncthreads();
        s[tid] += t;
        __syncthreads();
    }
    int incl = s[tid];
    if (tid == 0) {
        unsigned int aggregate = (unsigned int)s[1023];
        atomicExch(&gz.agg[bid], aggregate | 0x80000000u);
    }
    if (tid < 32) {
        unsigned int sum = 0;
        for (int b = tid; b < bid; b += 32) {
            unsigned int a;
            do { a = *(volatile unsigned int*)&gz.agg[b]; } while (!(a & 0x80000000u));
            sum += a & 0x7fffffffu;
        }
        #pragma unroll
        for (int off = 16; off; off >>= 1) sum += __shfl_xor_sync(0xffffffffu, sum, off);
        if (tid == 0) sprefix = (int)sum;
    }
    __syncthreads();
    if (i < NN) {
        int o = sprefix + incl - v;
        g_off[i] = o;
        g_cur[i] = o;
    }
}

// gather-free scatter (dis factors separable)
__global__ void k_scatter(const int* __restrict__ row, const int* __restrict__ colv,
                          const float* __restrict__ ew) {
    int e = blockIdx.x*blockDim.x + threadIdx.x;
    if (e < EE) {
        int r = row[e], c = colv[e];
        int p = atomicAdd(&g_cur[c], 1);
        unsigned short hb = __half_as_ushort(__float2half_rn(ew[e]));  // ew >= 0
        g_edge[p] = ((unsigned int)hb << 17) | (unsigned int)r;
    }
}

// ---------------- conv1 ----------------
// Half-warp per node: 16 lanes stride edges (unroll-2), 4-level reduce,
// then lanes 0..11 write the 16*dis-prescaled fp8 feature state.
__global__ void __launch_bounds__(256)
k_ax(const float* __restrict__ x, const float* __restrict__ iw,
     const float* __restrict__ rw, const float* __restrict__ bs) {
    int n = (blockIdx.x*256 + threadIdx.x) >> 4;   // grid exact: 6250*16 = 100000
    int lane = threadIdx.x & 15;
    int st = g_off[n], cn = g_cnt[n];
    int e_end = st + cn;
    float s = 0.f;
    int j = st + lane;
    for (; j + 16 < e_end; j += 32) {
        unsigned int u0 = g_edge[j];
        unsigned int u1 = g_edge[j+16];
        s += dnorm(u0) * __ldg(&g_xs[dsrc(u0)]);
        s += dnorm(u1) * __ldg(&g_xs[dsrc(u1)]);
    }
    if (j < e_end) {
        unsigned int u0 = g_edge[j];
        s += dnorm(u0) * __ldg(&g_xs[dsrc(u0)]);
    }
    #pragma unroll
    for (int off = 8; off; off >>= 1) s += __shfl_xor_sync(0xffffffffu, s, off);
    float disn = g_dis[n];
    s *= disn;                       // Ax[n]
    float xv = __ldg(&x[n]);
    if (lane < 12) {
        int k = lane % 3, cidx = lane / 3;
        int f = k*16 + cidx*4;
        float sc = F8SCALE * disn;
        float f0 = fmaxf(s*__ldg(&iw[f+0]) + xv*__ldg(&rw[f+0]) + __ldg(&bs[f+0]), 0.f);
        float f1 = fmaxf(s*__ldg(&iw[f+1]) + xv*__ldg(&rw[f+1]) + __ldg(&bs[f+1]), 0.f);
        float f2 = fmaxf(s*__ldg(&iw[f+2]) + xv*__ldg(&rw[f+2]) + __ldg(&bs[f+2]), 0.f);
        float f3 = fmaxf(s*__ldg(&iw[f+3]) + xv*__ldg(&rw[f+3]) + __ldg(&bs[f+3]), 0.f);
        g_fa[n*16 + cidx*3 + k] = pack4f8(sc*f0, sc*f1, sc*f2, sc*f3);
    }
}

// Warp per node, dual-edge halves, graduated unroll (8/4/2/1) fp8 gather.
// Lane c<12 loads one 4B word (4 fp8 feats) per edge -> 2 sectors/edge.
// acc = sum ew*(16*dis*out)_src; A(out) = (dis[n]/16)*acc (post-reduce).
// Epilogue: 16x16 W matmul over 24 lanes + root + relu; finalMode fuses
// mean/BN/relu + conv2 Horner prep.
__global__ void __launch_bounds__(256)
k_iter1(int srcIsB, int finalMode,
        const float* __restrict__ x, const float* __restrict__ w,
        const float* __restrict__ rw, const float* __restrict__ bs,
        const float* __restrict__ bng, const float* __restrict__ bnb,
        const float* __restrict__ bnm, const float* __restrict__ bnv,
        const float* __restrict__ iw2, const float* __restrict__ w2,
        const float* __restrict__ rw2, const float* __restrict__ b2) {
    __shared__ float wsh[768];
    __shared__ float rwsh[48], bsh[48];
    __shared__ float ex[8][56];
    for (int i = threadIdx.x; i < 768; i += 256) wsh[i] = w[i];
    if (threadIdx.x < 48) { rwsh[threadIdx.x] = rw[threadIdx.x]; bsh[threadIdx.x] = bs[threadIdx.x]; }
    __syncthreads();

    int warp = threadIdx.x >> 5;
    int lane = threadIdx.x & 31;
    int h = lane >> 4, c = lane & 15;
    bool act = c < 12;
    int n = blockIdx.x*8 + warp;                 // grid exact
    int st = g_off[n], cn = g_cnt[n];
    int e_end = st + cn;
    const unsigned int* F = srcIsB ? g_fb : g_fa;
    unsigned short*     D = (unsigned short*)(srcIsB ? g_fa : g_fb);

    float4 acc = make_float4(0.f, 0.f, 0.f, 0.f);
    int j = st + h;

    #define ACCUM(q, m) { \
        float4 _v = unpack4f8(q); \
        acc.x += (m)*_v.x; acc.y += (m)*_v.y; acc.z += (m)*_v.z; acc.w += (m)*_v.w; }

    while (j + 14 < e_end) {        // 8 edges per half
        unsigned int u0 = g_edge[j],    u1 = g_edge[j+2],  u2 = g_edge[j+4],  u3 = g_edge[j+6];
        unsigned int u4 = g_edge[j+8],  u5 = g_edge[j+10], u6 = g_edge[j+12], u7 = g_edge[j+14];
        int s0 = dsrc(u0), s1 = dsrc(u1), s2 = dsrc(u2), s3 = dsrc(u3);
        int s4 = dsrc(u4), s5 = dsrc(u5), s6 = dsrc(u6), s7 = dsrc(u7);
        if (act) {
            unsigned int q0 = __ldg(&F[s0*16 + c]);
            unsigned int q1 = __ldg(&F[s1*16 + c]);
            unsigned int q2 = __ldg(&F[s2*16 + c]);
            unsigned int q3 = __ldg(&F[s3*16 + c]);
            unsigned int q4 = __ldg(&F[s4*16 + c]);
            unsigned int q5 = __ldg(&F[s5*16 + c]);
            unsigned int q6 = __ldg(&F[s6*16 + c]);
            unsigned int q7 = __ldg(&F[s7*16 + c]);
            float m0 = dnorm(u0), m1 = dnorm(u1), m2 = dnorm(u2), m3 = dnorm(u3);
            float m4 = dnorm(u4), m5 = dnorm(u5), m6 = dnorm(u6), m7 = dnorm(u7);
            ACCUM(q0, m0); ACCUM(q1, m1); ACCUM(q2, m2); ACCUM(q3, m3);
            ACCUM(q4, m4); ACCUM(q5, m5); ACCUM(q6, m6); ACCUM(q7, m7);
        }
        j += 16;
    }
    if (j + 6 < e_end) {            // 4 edges per half
        unsigned int u0 = g_edge[j], u1 = g_edge[j+2], u2 = g_edge[j+4], u3 = g_edge[j+6];
        int s0 = dsrc(u0), s1 = dsrc(u1), s2 = dsrc(u2), s3 = dsrc(u3);
        if (act) {
            unsigned int q0 = __ldg(&F[s0*16 + c]);
            unsigned int q1 = __ldg(&F[s1*16 + c]);
            unsigned int q2 = __ldg(&F[s2*16 + c]);
            unsigned int q3 = __ldg(&F[s3*16 + c]);
            float m0 = dnorm(u0), m1 = dnorm(u1), m2 = dnorm(u2), m3 = dnorm(u3);
            ACCUM(q0, m0); ACCUM(q1, m1); ACCUM(q2, m2); ACCUM(q3, m3);
        }
        j += 8;
    }
    if (j + 2 < e_end) {            // 2 edges per half
        unsigned int u0 = g_edge[j], u1 = g_edge[j+2];
        int s0 = dsrc(u0), s1 = dsrc(u1);
        if (act) {
            unsigned int q0 = __ldg(&F[s0*16 + c]);
            unsigned int q1 = __ldg(&F[s1*16 + c]);
            float m0 = dnorm(u0), m1 = dnorm(u1);
            ACCUM(q0, m0); ACCUM(q1, m1);
        }
        j += 4;
    }
    if (j < e_end) {                // final edge
        unsigned int u0 = g_edge[j];
        int s0 = dsrc(u0);
        if (act) {
            unsigned int q0 = __ldg(&F[s0*16 + c]);
            float m0 = dnorm(u0);
            ACCUM(q0, m0);
        }
    }
    #undef ACCUM

    // combine the two halves, apply dis[n]/16 (dst normalization + fp8 unscale)
    float disn = g_dis[n];
    float post = disn * F8INV;
    acc.x += __shfl_xor_sync(0xffffffffu, acc.x, 16);
    acc.y += __shfl_xor_sync(0xffffffffu, acc.y, 16);
    acc.z += __shfl_xor_sync(0xffffffffu, acc.z, 16);
    acc.w += __shfl_xor_sync(0xffffffffu, acc.w, 16);
    acc.x *= post; acc.y *= post; acc.z *= post; acc.w *= post;

    int kk = c % 3, cidx = c / 3;   // chunk c = cidx*3 + kk
    bool act0 = (h == 0) && act;
    if (act0) {
        float* e = ex[warp] + kk*16 + cidx*4;
        e[0] = acc.x; e[1] = acc.y; e[2] = acc.z; e[3] = acc.w;
    }
    __syncwarp();

    // y = af * W[k] + x*root_w + bias, relu — split over 24 lanes
    float y0 = 0.f, y1 = 0.f;
    int oo = cidx*4 + h*2;
    if (act) {
        const float* af = ex[warp] + kk*16;
        const float* wk = wsh + kk*256;
        float xv = __ldg(&x[n]);
        #pragma unroll
        for (int f = 0; f < 16; f++) {
            float a = af[f];
            y0 += a * wk[f*16 + oo];
            y1 += a * wk[f*16 + oo + 1];
        }
        y0 = fmaxf(y0 + xv*rwsh[kk*16+oo]   + bsh[kk*16+oo],   0.f);
        y1 = fmaxf(y1 + xv*rwsh[kk*16+oo+1] + bsh[kk*16+oo+1], 0.f);
    }
    __syncwarp();

    if (!finalMode) {
        if (act) {
            float sc = F8SCALE * disn;       // prescale for next gather
            D[n*32 + c*2 + h] = pack2f8(sc*y0, sc*y1);
        }
        return;
    }

    // ---- final iteration: mean over stacks + BN + relu + conv2 Horner prep ----
    if (act) {
        ex[warp][kk*16 + oo + 0] = y0;
        ex[warp][kk*16 + oo + 1] = y1;
    }
    __syncwarp();
    if (lane < 16) {
        float m = (ex[warp][lane] + ex[warp][16+lane] + ex[warp][32+lane]) * (1.f/3.f);
        float sc = __ldg(&bng[lane]) * rsqrtf(__ldg(&bnv[lane]) + 1e-5f);
        ex[warp][lane] = fmaxf((m - __ldg(&bnm[lane]))*sc + __ldg(&bnb[lane]), 0.f);
    }
    __syncwarp();
    if (lane == 0) {
        float hv[16];
        #pragma unroll
        for (int f = 0; f < 16; f++) hv[f] = ex[warp][f];
        float o[3] = {0,0,0}, r[3] = {0,0,0};
        #pragma unroll
        for (int k2 = 0; k2 < 3; k2++) {
            #pragma unroll
            for (int f = 0; f < 16; f++) {
                o[k2] += hv[f] * __ldg(&iw2[k2*16+f]);
                r[k2] += hv[f] * __ldg(&rw2[k2*16+f]);
            }
            r[k2] += __ldg(&b2[k2]);
        }
        float z = 0.f, s3v = 0.f, s2v = 0.f, s1v = 0.f, s0v = 0.f;
        #pragma unroll
        for (int k2 = 0; k2 < 3; k2++) {
            float wv = __ldg(&w2[k2]);
            float w2p = wv*wv, w3p = w2p*wv;
            z   += w3p * o[k2];
            s3v += w3p * r[k2];
            s2v += w2p * r[k2];
            s1v += wv  * r[k2];
            s0v += r[k2];
        }
        g_ca[n] = z * disn;   // prescaled for the first k_sp gather
        float4 sv; sv.x = s3v; sv.y = s2v; sv.z = s1v; sv.w = s0v;
        g_s[n] = sv;
    }
}

// ---------------- conv2: 4 scalar Horner SpMV passes ----------------
__global__ void __launch_bounds__(256)
k_sp(int pass, float* __restrict__ finalOut) {
    int n = (blockIdx.x*256 + threadIdx.x) >> 4;   // grid exact: 6250*16 = 100000
    int lane = threadIdx.x & 15;
    int st = g_off[n], cn = g_cnt[n];
    int e_end = st + cn;
    const float* src = (pass & 1) ? g_cb : g_ca;
    float s = 0.f;
    int j = st + lane;
    for (; j + 16 < e_end; j += 32) {
        unsigned int u0 = g_edge[j];
        unsigned int u1 = g_edge[j+16];
        s += dnorm(u0) * __ldg(&src[dsrc(u0)]);
        s += dnorm(u1) * __ldg(&src[dsrc(u1)]);
    }
    if (j < e_end) {
        unsigned int u0 = g_edge[j];
        s += dnorm(u0) * __ldg(&src[dsrc(u0)]);
    }
    #pragma unroll
    for (int off = 8; off; off >>= 1) s += __shfl_xor_sync(0xffffffffu, s, off);
    if (lane == 0) {
        float disn = g_dis[n];
        float4 sv = __ldg(&g_s[n]);
        float si = (pass == 0) ? sv.x : (pass == 1) ? sv.y : (pass == 2) ? sv.z : sv.w;
        float cval = disn*s + si;
        if (pass == 3) {
            finalOut[n] = 1.f / (1.f + expf(-cval * (1.f/3.f)));
        } else {
            float* dst = (pass & 1) ? g_ca : g_cb;
            dst[n] = cval * disn;    // prescale for next gather
        }
    }
}

// ---------------- driver ----------------
extern "C" void kernel_launch(void* const* d_in, const int* in_sizes, int n_in,
                              void* d_out, int out_size) {
    const float* x    = (const float*)d_in[0];
    const int*   ei   = (const int*)  d_in[1];
    const float* ew   = (const float*)d_in[2];
    const float* c1iw = (const float*)d_in[3];
    const float* c1w  = (const float*)d_in[4];
    const float* c1rw = (const float*)d_in[5];
    const float* c1b  = (const float*)d_in[6];
    const float* bng  = (const float*)d_in[7];
    const float* bnb  = (const float*)d_in[8];
    const float* bnm  = (const float*)d_in[9];
    const float* bnv  = (const float*)d_in[10];
    const float* c2iw = (const float*)d_in[11];
    const float* c2w  = (const float*)d_in[12];
    const float* c2rw = (const float*)d_in[13];
    const float* c2b  = (const float*)d_in[14];
    float* out = (float*)d_out;

    const int* row = ei;
    const int* col = ei + EE;

    const int EG = (EE + 255) / 256;
    const int WG = 12500;   // warp-per-node: 12500 blocks x 8 warps = 100000
    const int HG = 6250;    // half-warp-per-node: 6250 blocks x 16 halves = 100000

    void* zp = nullptr;
    cudaGetSymbolAddress(&zp, gz);
    cudaMemsetAsync(zp, 0, sizeof(ZBlock), 0);

    // gcn_norm + CSR build (scatter is gather-free; dis factors separable)
    k_deg<<<EG, 256>>>(col, ew);
    k_scan<<<NBLK, 1024>>>(x);
    k_scatter<<<EG, 256>>>(row, col, ew);

    // conv1: rank-1 first propagation (+fused feature init), then 3 SpMM iters
    k_ax<<<HG, 256>>>(x, c1iw, c1rw, c1b);
    k_iter1<<<WG, 256>>>(0, 0, x, c1w, c1rw, c1b, bng, bnb, bnm, bnv, c2iw, c2w, c2rw, c2b); // fa -> fb
    k_iter1<<<WG, 256>>>(1, 0, x, c1w, c1rw, c1b, bng, bnb, bnm, bnv, c2iw, c2w, c2rw, c2b); // fb -> fa
    k_iter1<<<WG, 256>>>(0, 1, x, c1w, c1rw, c1b, bng, bnb, bnm, bnv, c2iw, c2w, c2rw, c2b); // fa -> Horner prep

    // conv2: 4 scalar Horner passes, last fuses sigmoid -> out
    k_sp<<<HG, 256>>>(0, nullptr);  // ca -> cb  (+s3)
    k_sp<<<HG, 256>>>(1, nullptr);  // cb -> ca  (+s2)
    k_sp<<<HG, 256>>>(2, nullptr);  // ca -> cb  (+s1)
    k_sp<<<HG, 256>>>(3, out);      // cb -> sigmoid((c+s0)/3) -> out
}